// round 2
// baseline (speedup 1.0000x reference)
#include <cuda_runtime.h>
#include <cstdint>
#include <math.h>

// ---------------- problem constants ----------------
#define TOK      8192          // B*S tokens
#define HID      2048
#define FFN      7168
#define NE       8
#define NPAIR    (TOK * 2)     // top-2 -> exactly 16384 (token, expert) pairs
#define OUT_ELEMS ((size_t)TOK * HID)
#define MT       128           // GEMM m-tile rows
#define MAXT     136           // 16384/128 + 8

// ---------------- device scratch ----------------
__device__ int   g_cnt[NE];
__device__ int   g_off[NE];
__device__ int   g_cur[NE];
__device__ int   g_ntiles;
__device__ int   g_tile_e[MAXT];
__device__ int   g_tile_m[MAXT];
__device__ int   g_sel[NPAIR];
__device__ float g_selw[NPAIR];
__device__ int   g_ptok[NPAIR];
__device__ float g_pw[NPAIR];
__device__ int   g_pe[NPAIR];
__device__ float g_logit_dump[TOK * NE];
__device__ float g_xg[(size_t)NPAIR * HID];      // gathered scaled activations (tf32-rounded)
__device__ float g_hmid[(size_t)NPAIR * FFN];    // silu(xw1)*(xw3)*w_r (tf32-rounded)

// ---------------- helpers ----------------
__device__ __forceinline__ float to_tf32(float x) {
    unsigned u;
    asm("cvt.rna.tf32.f32 %0, %1;" : "=r"(u) : "f"(x));
    return __uint_as_float(u);
}

__device__ __forceinline__ void mma_tf32(float c[4], const unsigned a[4], const unsigned b[2]) {
    asm volatile(
        "mma.sync.aligned.m16n8k8.row.col.f32.tf32.tf32.f32 "
        "{%0,%1,%2,%3}, {%4,%5,%6,%7}, {%8,%9}, {%0,%1,%2,%3};\n"
        : "+f"(c[0]), "+f"(c[1]), "+f"(c[2]), "+f"(c[3])
        : "r"(a[0]), "r"(a[1]), "r"(a[2]), "r"(a[3]), "r"(b[0]), "r"(b[1]));
}

__device__ __forceinline__ void cp_async16(uint32_t saddr, const void* gptr, int szbytes) {
    asm volatile("cp.async.cg.shared.global [%0], [%1], 16, %2;\n"
                 :: "r"(saddr), "l"(gptr), "r"(szbytes));
}
#define CP_COMMIT() asm volatile("cp.async.commit_group;\n" ::)
#define CP_WAIT(n)  asm volatile("cp.async.wait_group %0;\n" :: "n"(n))

// ---------------- kernel 0: zero output + counters ----------------
__global__ void init_kernel(float4* out4) {
    size_t i      = (size_t)blockIdx.x * blockDim.x + threadIdx.x;
    size_t stride = (size_t)gridDim.x * blockDim.x;
    const size_t n4 = OUT_ELEMS / 4;
    float4 z = make_float4(0.f, 0.f, 0.f, 0.f);
    for (size_t j = i; j < n4; j += stride) out4[j] = z;
    if (blockIdx.x == 0 && threadIdx.x < NE) g_cnt[threadIdx.x] = 0;
}

// ---------------- kernel 1: router ----------------
__global__ void router_kernel(const float* __restrict__ x,
                              const float* __restrict__ gate,
                              float* __restrict__ logits_out,
                              int write_logits) {
    int warp = threadIdx.x >> 5;
    int lane = threadIdx.x & 31;
    int tbase = blockIdx.x * 64 + warp * 8;

    for (int i = 0; i < 8; i++) {
        int t = tbase + i;
        const float4* xp = (const float4*)(x + (size_t)t * HID);
        float acc[NE];
#pragma unroll
        for (int e = 0; e < NE; e++) acc[e] = 0.f;

        for (int c = lane; c < HID / 4; c += 32) {
            float4 xv = __ldg(xp + c);
#pragma unroll
            for (int e = 0; e < NE; e++) {
                float4 gv = __ldg((const float4*)(gate + (size_t)e * HID) + c);
                acc[e] += xv.x * gv.x + xv.y * gv.y + xv.z * gv.z + xv.w * gv.w;
            }
        }
#pragma unroll
        for (int e = 0; e < NE; e++)
            for (int o = 16; o; o >>= 1) acc[e] += __shfl_xor_sync(0xffffffffu, acc[e], o);

        if (lane == 0) {
            float* lo = write_logits ? logits_out : g_logit_dump;
#pragma unroll
            for (int e = 0; e < NE; e++) lo[(size_t)t * NE + e] = acc[e];

            int e0 = 0;
            for (int e = 1; e < NE; e++) if (acc[e] > acc[e0]) e0 = e;
            int e1 = -1;
            for (int e = 0; e < NE; e++) {
                if (e == e0) continue;
                if (e1 < 0 || acc[e] > acc[e1]) e1 = e;
            }
            float w0 = 1.f / (1.f + expf(acc[e1] - acc[e0]));
            float w1 = 1.f - w0;
            g_sel[t * 2 + 0] = e0; g_selw[t * 2 + 0] = w0;
            g_sel[t * 2 + 1] = e1; g_selw[t * 2 + 1] = w1;
            atomicAdd(&g_cnt[e0], 1);
            atomicAdd(&g_cnt[e1], 1);
        }
    }
}

// ---------------- kernel 2: scan + tile list ----------------
__global__ void scan_kernel() {
    if (threadIdx.x == 0) {
        int o = 0, nt = 0;
        for (int e = 0; e < NE; e++) {
            g_off[e] = o;
            g_cur[e] = o;
            int c = g_cnt[e];
            int tl = (c + MT - 1) / MT;
            for (int m = 0; m < tl; m++) { g_tile_e[nt] = e; g_tile_m[nt] = m; nt++; }
            o += c;
        }
        g_ntiles = nt;
    }
}

// ---------------- kernel 3: scatter ----------------
__global__ void scatter_kernel() {
    int t = blockIdx.x * blockDim.x + threadIdx.x;
    if (t >= TOK) return;
#pragma unroll
    for (int k = 0; k < 2; k++) {
        int e = g_sel[t * 2 + k];
        int pos = atomicAdd(&g_cur[e], 1);
        g_ptok[pos] = t;
        g_pw[pos]   = g_selw[t * 2 + k];
        g_pe[pos]   = e;
    }
}

// ---------------- kernel 4: gather + scale divide (tf32-rounded output) ----------------
__global__ void gather_kernel(const float* __restrict__ x,
                              const float* __restrict__ scales) {
    int r = blockIdx.x;
    int tok = g_ptok[r];
    int e   = g_pe[r];
    const float4* xp = (const float4*)(x + (size_t)tok * HID);
    const float4* sp = (const float4*)(scales + (size_t)e * HID);
    float4* dp = (float4*)(g_xg + (size_t)r * HID);
    for (int c = threadIdx.x; c < HID / 4; c += blockDim.x) {
        float4 xv = xp[c], sv = sp[c];
        float4 o;
        o.x = to_tf32(xv.x / sv.x); o.y = to_tf32(xv.y / sv.y);
        o.z = to_tf32(xv.z / sv.z); o.w = to_tf32(xv.w / sv.w);
        dp[c] = o;
    }
}

// ---------------- GEMM config ----------------
#define BK  16
#define PAD 20

// ---------------- kernel 5: GEMM-1 (w1 & w3) + SiLU + routing weight ----------------
// 128x64 tile per matrix. A via cp.async double-buffer; B via LDG->cvt->STS staging.
__global__ __launch_bounds__(256, 2) void gemm1_kernel(const float* __restrict__ w1,
                                                       const float* __restrict__ w3) {
    int ti = blockIdx.y;
    if (ti >= g_ntiles) return;
    int e   = g_tile_e[ti];
    int mt  = g_tile_m[ti];
    int cnt = g_cnt[e];
    int off = g_off[e];
    int row0  = off + mt * MT;
    int mrows = cnt - mt * MT; if (mrows > MT) mrows = MT;
    int n0 = blockIdx.x * 64;

    __shared__ float As[2][MT][PAD];
    __shared__ float B1s[2][64][PAD];
    __shared__ float B3s[2][64][PAD];

    int tid = threadIdx.x;
    const float* w1p = w1 + ((size_t)e * FFN + n0) * HID;
    const float* w3p = w3 + ((size_t)e * FFN + n0) * HID;

    // A load mapping: 2 float4 per thread
    int ar0 = tid >> 1;                      // row (same for j=0,1)
    // B load mapping: 1 float4 per matrix per thread
    int brow = tid >> 2;
    int bc4  = tid & 3;

    // warp tiling: 4 m-warps x 2 n-warps, warp tile 32m x 32n per matrix
    int wid = tid >> 5, lane = tid & 31;
    int wm = (wid & 3) * 32;
    int wn = (wid >> 2) * 32;
    int lr = lane >> 2, lc = lane & 3;

    float c1[2][4][4], c2[2][4][4];
#pragma unroll
    for (int i = 0; i < 2; i++)
#pragma unroll
        for (int j = 0; j < 4; j++)
#pragma unroll
            for (int q = 0; q < 4; q++) { c1[i][j][q] = 0.f; c2[i][j][q] = 0.f; }

    float4 s1, s3;  // B staging

    // --- pipeline helpers (macros-by-lambda) ---
    auto loadA = [&](int buf, int k0) {
#pragma unroll
        for (int j = 0; j < 2; j++) {
            int idx = 2 * tid + j;
            int row = idx >> 2;
            int c4  = idx & 3;
            bool p = row < mrows;
            const float* src = g_xg + (size_t)(row0 + (p ? row : 0)) * HID + k0 + c4 * 4;
            uint32_t sa = (uint32_t)__cvta_generic_to_shared(&As[buf][row][c4 * 4]);
            cp_async16(sa, src, p ? 16 : 0);
        }
    };
    auto ldgB = [&](int k0) {
        s1 = *(const float4*)(w1p + (size_t)brow * HID + k0 + bc4 * 4);
        s3 = *(const float4*)(w3p + (size_t)brow * HID + k0 + bc4 * 4);
    };
    auto stsB = [&](int buf) {
        float4 t1, t3;
        t1.x = to_tf32(s1.x); t1.y = to_tf32(s1.y); t1.z = to_tf32(s1.z); t1.w = to_tf32(s1.w);
        t3.x = to_tf32(s3.x); t3.y = to_tf32(s3.y); t3.z = to_tf32(s3.z); t3.w = to_tf32(s3.w);
        *(float4*)(&B1s[buf][brow][bc4 * 4]) = t1;
        *(float4*)(&B3s[buf][brow][bc4 * 4]) = t3;
    };

    const int nk = HID / BK;   // 128

    loadA(0, 0); CP_COMMIT();
    ldgB(0);
    stsB(0);
    loadA(1, BK); CP_COMMIT();
    ldgB(BK);
    CP_WAIT(1);
    __syncthreads();

    for (int i = 0; i < nk; i++) {
        int cur = i & 1, nxt = cur ^ 1;
        // compute tile i from buf[cur]
#pragma unroll
        for (int kk = 0; kk < BK; kk += 8) {
            unsigned a[2][4], b1[4][2], b3[4][2];
#pragma unroll
            for (int sm = 0; sm < 2; sm++) {
                int arr = wm + sm * 16 + lr;
                a[sm][0] = __float_as_uint(As[cur][arr][kk + lc]);
                a[sm][1] = __float_as_uint(As[cur][arr + 8][kk + lc]);
                a[sm][2] = __float_as_uint(As[cur][arr][kk + 4 + lc]);
                a[sm][3] = __float_as_uint(As[cur][arr + 8][kk + 4 + lc]);
            }
#pragma unroll
            for (int sn = 0; sn < 4; sn++) {
                int br = wn + sn * 8 + lr;
                b1[sn][0] = __float_as_uint(B1s[cur][br][kk + lc]);
                b1[sn][1] = __float_as_uint(B1s[cur][br][kk + 4 + lc]);
                b3[sn][0] = __float_as_uint(B3s[cur][br][kk + lc]);
                b3[sn][1] = __float_as_uint(B3s[cur][br][kk + 4 + lc]);
            }
#pragma unroll
            for (int sm = 0; sm < 2; sm++)
#pragma unroll
                for (int sn = 0; sn < 4; sn++) {
                    mma_tf32(c1[sm][sn], a[sm], b1[sn]);
                    mma_tf32(c2[sm][sn], a[sm], b3[sn]);
                }
        }
        __syncthreads();
        if (i + 1 < nk) {
            stsB(nxt);
            if (i + 2 < nk) {
                ldgB((i + 2) * BK);
                loadA(cur, (i + 2) * BK); CP_COMMIT();
                CP_WAIT(1);
            } else {
                CP_WAIT(0);
            }
            __syncthreads();
        }
    }

    // epilogue: hmid = silu(c1) * c2 * routing_weight (tf32-rounded)
#pragma unroll
    for (int sm = 0; sm < 2; sm++) {
        int rbase = wm + sm * 16 + lr;
#pragma unroll
        for (int half = 0; half < 2; half++) {
            int r = rbase + half * 8;
            if (r < mrows) {
                float wr = g_pw[row0 + r];
                float* hp = g_hmid + (size_t)(row0 + r) * FFN + n0;
#pragma unroll
                for (int sn = 0; sn < 4; sn++) {
                    int col = wn + sn * 8 + lc * 2;
                    float v1a = c1[sm][sn][half * 2 + 0], v3a = c2[sm][sn][half * 2 + 0];
                    float v1b = c1[sm][sn][half * 2 + 1], v3b = c2[sm][sn][half * 2 + 1];
                    hp[col + 0] = to_tf32((v1a / (1.f + expf(-v1a))) * v3a * wr);
                    hp[col + 1] = to_tf32((v1b / (1.f + expf(-v1b))) * v3b * wr);
                }
            }
        }
    }
}

// ---------------- kernel 6: GEMM-2 (hmid @ w2^T) + scatter-add ----------------
// 128x128 tile. A via cp.async double-buffer; B via LDG->cvt->STS staging.
__global__ __launch_bounds__(256, 2) void gemm2_kernel(const float* __restrict__ w2,
                                                       float* __restrict__ out) {
    int ti = blockIdx.y;
    if (ti >= g_ntiles) return;
    int e   = g_tile_e[ti];
    int mt  = g_tile_m[ti];
    int cnt = g_cnt[e];
    int off = g_off[e];
    int row0  = off + mt * MT;
    int mrows = cnt - mt * MT; if (mrows > MT) mrows = MT;
    int n0 = blockIdx.x * 128;   // over HID

    __shared__ float As[2][MT][PAD];
    __shared__ float Bs[2][128][PAD];

    int tid = threadIdx.x;
    const float* w2p = w2 + ((size_t)e * HID + n0) * FFN;

    // warp tiling: 4 m-warps x 2 n-warps, warp tile 32m x 64n
    int wid = tid >> 5, lane = tid & 31;
    int wm = (wid & 3) * 32;
    int wn = (wid >> 2) * 64;
    int lr = lane >> 2, lc = lane & 3;

    float cc[2][8][4];
#pragma unroll
    for (int i = 0; i < 2; i++)
#pragma unroll
        for (int j = 0; j < 8; j++)
#pragma unroll
            for (int q = 0; q < 4; q++) cc[i][j][q] = 0.f;

    float4 sb[2];  // B staging: 128x16 / 256 threads = 2 float4

    auto loadA = [&](int buf, int k0) {
#pragma unroll
        for (int j = 0; j < 2; j++) {
            int idx = 2 * tid + j;
            int row = idx >> 2;
            int c4  = idx & 3;
            bool p = row < mrows;
            const float* src = g_hmid + (size_t)(row0 + (p ? row : 0)) * FFN + k0 + c4 * 4;
            uint32_t sa = (uint32_t)__cvta_generic_to_shared(&As[buf][row][c4 * 4]);
            cp_async16(sa, src, p ? 16 : 0);
        }
    };
    auto ldgB = [&](int k0) {
#pragma unroll
        for (int q = 0; q < 2; q++) {
            int idx = tid + q * 256;
            int row = idx >> 2;
            int c4  = idx & 3;
            sb[q] = *(const float4*)(w2p + (size_t)row * FFN + k0 + c4 * 4);
        }
    };
    auto stsB = [&](int buf) {
#pragma unroll
        for (int q = 0; q < 2; q++) {
            int idx = tid + q * 256;
            int row = idx >> 2;
            int c4  = idx & 3;
            float4 t;
            t.x = to_tf32(sb[q].x); t.y = to_tf32(sb[q].y);
            t.z = to_tf32(sb[q].z); t.w = to_tf32(sb[q].w);
            *(float4*)(&Bs[buf][row][c4 * 4]) = t;
        }
    };

    const int nk = FFN / BK;   // 448

    loadA(0, 0); CP_COMMIT();
    ldgB(0);
    stsB(0);
    loadA(1, BK); CP_COMMIT();
    ldgB(BK);
    CP_WAIT(1);
    __syncthreads();

    for (int i = 0; i < nk; i++) {
        int cur = i & 1, nxt = cur ^ 1;
#pragma unroll
        for (int kk = 0; kk < BK; kk += 8) {
            unsigned a[2][4], b[8][2];
#pragma unroll
            for (int sm = 0; sm < 2; sm++) {
                int arr = wm + sm * 16 + lr;
                a[sm][0] = __float_as_uint(As[cur][arr][kk + lc]);
                a[sm][1] = __float_as_uint(As[cur][arr + 8][kk + lc]);
                a[sm][2] = __float_as_uint(As[cur][arr][kk + 4 + lc]);
                a[sm][3] = __float_as_uint(As[cur][arr + 8][kk + 4 + lc]);
            }
#pragma unroll
            for (int sn = 0; sn < 8; sn++) {
                int br = wn + sn * 8 + lr;
                b[sn][0] = __float_as_uint(Bs[cur][br][kk + lc]);
                b[sn][1] = __float_as_uint(Bs[cur][br][kk + 4 + lc]);
            }
#pragma unroll
            for (int sm = 0; sm < 2; sm++)
#pragma unroll
                for (int sn = 0; sn < 8; sn++)
                    mma_tf32(cc[sm][sn], a[sm], b[sn]);
        }
        __syncthreads();
        if (i + 1 < nk) {
            stsB(nxt);
            if (i + 2 < nk) {
                ldgB((i + 2) * BK);
                loadA(cur, (i + 2) * BK); CP_COMMIT();
                CP_WAIT(1);
            } else {
                CP_WAIT(0);
            }
            __syncthreads();
        }
    }

    // epilogue: atomic scatter-add into out[token][h]
#pragma unroll
    for (int sm = 0; sm < 2; sm++) {
        int rbase = wm + sm * 16 + lr;
#pragma unroll
        for (int half = 0; half < 2; half++) {
            int r = rbase + half * 8;
            if (r < mrows) {
                int tok = g_ptok[row0 + r];
                float* op = out + (size_t)tok * HID + n0;
#pragma unroll
                for (int sn = 0; sn < 8; sn++) {
                    int col = wn + sn * 8 + lc * 2;
                    atomicAdd(&op[col + 0], cc[sm][sn][half * 2 + 0]);
                    atomicAdd(&op[col + 1], cc[sm][sn][half * 2 + 1]);
                }
            }
        }
    }
}

// ---------------- host launch ----------------
extern "C" void kernel_launch(void* const* d_in, const int* in_sizes, int n_in,
                              void* d_out, int out_size) {
    const float* x      = (const float*)d_in[0];
    const float* gate   = (const float*)d_in[1];
    const float* w1     = (const float*)d_in[2];
    const float* w3     = (const float*)d_in[3];
    const float* w2     = (const float*)d_in[4];
    const float* scales = (const float*)d_in[5];

    float* out = (float*)d_out;
    int write_logits = ((size_t)out_size >= OUT_ELEMS + (size_t)TOK * NE) ? 1 : 0;
    float* logits = out + OUT_ELEMS;

    init_kernel<<<2048, 256>>>((float4*)out);
    router_kernel<<<TOK / 64, 256>>>(x, gate, logits, write_logits);
    scan_kernel<<<1, 32>>>();
    scatter_kernel<<<TOK / 256, 256>>>();
    gather_kernel<<<NPAIR, 128>>>(x, scales);

    dim3 g1(FFN / 64, MAXT);
    gemm1_kernel<<<g1, 256>>>(w1, w3);

    dim3 g2(HID / 128, MAXT);
    gemm2_kernel<<<g2, 256>>>(w2, out);
}

// round 3
// speedup vs baseline: 1.5790x; 1.5790x over previous
#include <cuda_runtime.h>
#include <cstdint>
#include <math.h>

// ---------------- problem constants ----------------
#define TOK      8192          // B*S tokens
#define HID      2048
#define FFN      7168
#define NE       8
#define NPAIR    (TOK * 2)     // top-2 -> exactly 16384 (token, expert) pairs
#define OUT_ELEMS ((size_t)TOK * HID)
#define MT       128           // GEMM m-tile rows
#define MAXT     136           // 16384/128 + 8

// ---------------- device scratch ----------------
__device__ int   g_cnt[NE];
__device__ int   g_off[NE];
__device__ int   g_cur[NE];
__device__ int   g_ntiles;
__device__ int   g_tile_e[MAXT];
__device__ int   g_tile_m[MAXT];
__device__ int   g_sel[NPAIR];
__device__ float g_selw[NPAIR];
__device__ int   g_ptok[NPAIR];
__device__ float g_pw[NPAIR];
__device__ int   g_pe[NPAIR];
__device__ float g_logit_dump[TOK * NE];
__device__ float g_xg[(size_t)NPAIR * HID];      // gathered scaled activations (tf32-rounded)
__device__ float g_hmid[(size_t)NPAIR * FFN];    // silu(xw1)*(xw3)*w_r (tf32-rounded)

// ---------------- helpers ----------------
__device__ __forceinline__ float to_tf32(float x) {
    unsigned u;
    asm("cvt.rna.tf32.f32 %0, %1;" : "=r"(u) : "f"(x));
    return __uint_as_float(u);
}

__device__ __forceinline__ void mma_tf32(float c[4], const unsigned a[4], const unsigned b[2]) {
    asm volatile(
        "mma.sync.aligned.m16n8k8.row.col.f32.tf32.tf32.f32 "
        "{%0,%1,%2,%3}, {%4,%5,%6,%7}, {%8,%9}, {%0,%1,%2,%3};\n"
        : "+f"(c[0]), "+f"(c[1]), "+f"(c[2]), "+f"(c[3])
        : "r"(a[0]), "r"(a[1]), "r"(a[2]), "r"(a[3]), "r"(b[0]), "r"(b[1]));
}

__device__ __forceinline__ void cp_async16(uint32_t saddr, const void* gptr, int szbytes) {
    asm volatile("cp.async.cg.shared.global [%0], [%1], 16, %2;\n"
                 :: "r"(saddr), "l"(gptr), "r"(szbytes));
}
#define CP_COMMIT() asm volatile("cp.async.commit_group;\n" ::)
#define CP_WAIT(n)  asm volatile("cp.async.wait_group %0;\n" :: "n"(n))

// ---------------- kernel 0: zero output + counters ----------------
__global__ void init_kernel(float4* out4) {
    size_t i      = (size_t)blockIdx.x * blockDim.x + threadIdx.x;
    size_t stride = (size_t)gridDim.x * blockDim.x;
    const size_t n4 = OUT_ELEMS / 4;
    float4 z = make_float4(0.f, 0.f, 0.f, 0.f);
    for (size_t j = i; j < n4; j += stride) out4[j] = z;
    if (blockIdx.x == 0 && threadIdx.x < NE) g_cnt[threadIdx.x] = 0;
}

// ---------------- kernel 1: router ----------------
__global__ void router_kernel(const float* __restrict__ x,
                              const float* __restrict__ gate,
                              float* __restrict__ logits_out,
                              int write_logits) {
    int warp = threadIdx.x >> 5;
    int lane = threadIdx.x & 31;
    int tbase = blockIdx.x * 64 + warp * 8;

    for (int i = 0; i < 8; i++) {
        int t = tbase + i;
        const float4* xp = (const float4*)(x + (size_t)t * HID);
        float acc[NE];
#pragma unroll
        for (int e = 0; e < NE; e++) acc[e] = 0.f;

        for (int c = lane; c < HID / 4; c += 32) {
            float4 xv = __ldg(xp + c);
#pragma unroll
            for (int e = 0; e < NE; e++) {
                float4 gv = __ldg((const float4*)(gate + (size_t)e * HID) + c);
                acc[e] += xv.x * gv.x + xv.y * gv.y + xv.z * gv.z + xv.w * gv.w;
            }
        }
#pragma unroll
        for (int e = 0; e < NE; e++)
            for (int o = 16; o; o >>= 1) acc[e] += __shfl_xor_sync(0xffffffffu, acc[e], o);

        if (lane == 0) {
            float* lo = write_logits ? logits_out : g_logit_dump;
#pragma unroll
            for (int e = 0; e < NE; e++) lo[(size_t)t * NE + e] = acc[e];

            int e0 = 0;
            for (int e = 1; e < NE; e++) if (acc[e] > acc[e0]) e0 = e;
            int e1 = -1;
            for (int e = 0; e < NE; e++) {
                if (e == e0) continue;
                if (e1 < 0 || acc[e] > acc[e1]) e1 = e;
            }
            float w0 = 1.f / (1.f + expf(acc[e1] - acc[e0]));
            float w1 = 1.f - w0;
            g_sel[t * 2 + 0] = e0; g_selw[t * 2 + 0] = w0;
            g_sel[t * 2 + 1] = e1; g_selw[t * 2 + 1] = w1;
            atomicAdd(&g_cnt[e0], 1);
            atomicAdd(&g_cnt[e1], 1);
        }
    }
}

// ---------------- kernel 2: scan + tile list ----------------
__global__ void scan_kernel() {
    if (threadIdx.x == 0) {
        int o = 0, nt = 0;
        for (int e = 0; e < NE; e++) {
            g_off[e] = o;
            g_cur[e] = o;
            int c = g_cnt[e];
            int tl = (c + MT - 1) / MT;
            for (int m = 0; m < tl; m++) { g_tile_e[nt] = e; g_tile_m[nt] = m; nt++; }
            o += c;
        }
        g_ntiles = nt;
    }
}

// ---------------- kernel 3: scatter ----------------
__global__ void scatter_kernel() {
    int t = blockIdx.x * blockDim.x + threadIdx.x;
    if (t >= TOK) return;
#pragma unroll
    for (int k = 0; k < 2; k++) {
        int e = g_sel[t * 2 + k];
        int pos = atomicAdd(&g_cur[e], 1);
        g_ptok[pos] = t;
        g_pw[pos]   = g_selw[t * 2 + k];
        g_pe[pos]   = e;
    }
}

// ---------------- kernel 4: gather + scale divide (tf32-rounded output) ----------------
__global__ void gather_kernel(const float* __restrict__ x,
                              const float* __restrict__ scales) {
    int r = blockIdx.x;
    int tok = g_ptok[r];
    int e   = g_pe[r];
    const float4* xp = (const float4*)(x + (size_t)tok * HID);
    const float4* sp = (const float4*)(scales + (size_t)e * HID);
    float4* dp = (float4*)(g_xg + (size_t)r * HID);
    for (int c = threadIdx.x; c < HID / 4; c += blockDim.x) {
        float4 xv = xp[c], sv = sp[c];
        float4 o;
        o.x = to_tf32(xv.x / sv.x); o.y = to_tf32(xv.y / sv.y);
        o.z = to_tf32(xv.z / sv.z); o.w = to_tf32(xv.w / sv.w);
        dp[c] = o;
    }
}

// ---------------- GEMM config ----------------
#define BK  16
#define PAD 20

// ---------------- kernel 5: GEMM-1 (w1 & w3) + SiLU + routing weight ----------------
// 128x64 tile per matrix. A via cp.async double-buffer; B via LDG->cvt->STS staging.
__global__ __launch_bounds__(256, 2) void gemm1_kernel(const float* __restrict__ w1,
                                                       const float* __restrict__ w3) {
    int ti = blockIdx.y;
    if (ti >= g_ntiles) return;
    int e   = g_tile_e[ti];
    int mt  = g_tile_m[ti];
    int cnt = g_cnt[e];
    int off = g_off[e];
    int row0  = off + mt * MT;
    int mrows = cnt - mt * MT; if (mrows > MT) mrows = MT;
    int n0 = blockIdx.x * 64;

    __shared__ float As[2][MT][PAD];
    __shared__ float B1s[2][64][PAD];
    __shared__ float B3s[2][64][PAD];

    int tid = threadIdx.x;
    const float* w1p = w1 + ((size_t)e * FFN + n0) * HID;
    const float* w3p = w3 + ((size_t)e * FFN + n0) * HID;

    // A load mapping: 2 float4 per thread
    int ar0 = tid >> 1;                      // row (same for j=0,1)
    // B load mapping: 1 float4 per matrix per thread
    int brow = tid >> 2;
    int bc4  = tid & 3;

    // warp tiling: 4 m-warps x 2 n-warps, warp tile 32m x 32n per matrix
    int wid = tid >> 5, lane = tid & 31;
    int wm = (wid & 3) * 32;
    int wn = (wid >> 2) * 32;
    int lr = lane >> 2, lc = lane & 3;

    float c1[2][4][4], c2[2][4][4];
#pragma unroll
    for (int i = 0; i < 2; i++)
#pragma unroll
        for (int j = 0; j < 4; j++)
#pragma unroll
            for (int q = 0; q < 4; q++) { c1[i][j][q] = 0.f; c2[i][j][q] = 0.f; }

    float4 s1, s3;  // B staging

    // --- pipeline helpers (macros-by-lambda) ---
    auto loadA = [&](int buf, int k0) {
#pragma unroll
        for (int j = 0; j < 2; j++) {
            int idx = 2 * tid + j;
            int row = idx >> 2;
            int c4  = idx & 3;
            bool p = row < mrows;
            const float* src = g_xg + (size_t)(row0 + (p ? row : 0)) * HID + k0 + c4 * 4;
            uint32_t sa = (uint32_t)__cvta_generic_to_shared(&As[buf][row][c4 * 4]);
            cp_async16(sa, src, p ? 16 : 0);
        }
    };
    auto ldgB = [&](int k0) {
        s1 = *(const float4*)(w1p + (size_t)brow * HID + k0 + bc4 * 4);
        s3 = *(const float4*)(w3p + (size_t)brow * HID + k0 + bc4 * 4);
    };
    auto stsB = [&](int buf) {
        float4 t1, t3;
        t1.x = to_tf32(s1.x); t1.y = to_tf32(s1.y); t1.z = to_tf32(s1.z); t1.w = to_tf32(s1.w);
        t3.x = to_tf32(s3.x); t3.y = to_tf32(s3.y); t3.z = to_tf32(s3.z); t3.w = to_tf32(s3.w);
        *(float4*)(&B1s[buf][brow][bc4 * 4]) = t1;
        *(float4*)(&B3s[buf][brow][bc4 * 4]) = t3;
    };

    const int nk = HID / BK;   // 128

    loadA(0, 0); CP_COMMIT();
    ldgB(0);
    stsB(0);
    loadA(1, BK); CP_COMMIT();
    ldgB(BK);
    CP_WAIT(1);
    __syncthreads();

    for (int i = 0; i < nk; i++) {
        int cur = i & 1, nxt = cur ^ 1;
        // compute tile i from buf[cur]
#pragma unroll
        for (int kk = 0; kk < BK; kk += 8) {
            unsigned a[2][4], b1[4][2], b3[4][2];
#pragma unroll
            for (int sm = 0; sm < 2; sm++) {
                int arr = wm + sm * 16 + lr;
                a[sm][0] = __float_as_uint(As[cur][arr][kk + lc]);
                a[sm][1] = __float_as_uint(As[cur][arr + 8][kk + lc]);
                a[sm][2] = __float_as_uint(As[cur][arr][kk + 4 + lc]);
                a[sm][3] = __float_as_uint(As[cur][arr + 8][kk + 4 + lc]);
            }
#pragma unroll
            for (int sn = 0; sn < 4; sn++) {
                int br = wn + sn * 8 + lr;
                b1[sn][0] = __float_as_uint(B1s[cur][br][kk + lc]);
                b1[sn][1] = __float_as_uint(B1s[cur][br][kk + 4 + lc]);
                b3[sn][0] = __float_as_uint(B3s[cur][br][kk + lc]);
                b3[sn][1] = __float_as_uint(B3s[cur][br][kk + 4 + lc]);
            }
#pragma unroll
            for (int sm = 0; sm < 2; sm++)
#pragma unroll
                for (int sn = 0; sn < 4; sn++) {
                    mma_tf32(c1[sm][sn], a[sm], b1[sn]);
                    mma_tf32(c2[sm][sn], a[sm], b3[sn]);
                }
        }
        __syncthreads();
        if (i + 1 < nk) {
            stsB(nxt);
            if (i + 2 < nk) {
                ldgB((i + 2) * BK);
                loadA(cur, (i + 2) * BK); CP_COMMIT();
                CP_WAIT(1);
            } else {
                CP_WAIT(0);
            }
            __syncthreads();
        }
    }

    // epilogue: hmid = silu(c1) * c2 * routing_weight (tf32-rounded)
#pragma unroll
    for (int sm = 0; sm < 2; sm++) {
        int rbase = wm + sm * 16 + lr;
#pragma unroll
        for (int half = 0; half < 2; half++) {
            int r = rbase + half * 8;
            if (r < mrows) {
                float wr = g_pw[row0 + r];
                float* hp = g_hmid + (size_t)(row0 + r) * FFN + n0;
#pragma unroll
                for (int sn = 0; sn < 4; sn++) {
                    int col = wn + sn * 8 + lc * 2;
                    float v1a = c1[sm][sn][half * 2 + 0], v3a = c2[sm][sn][half * 2 + 0];
                    float v1b = c1[sm][sn][half * 2 + 1], v3b = c2[sm][sn][half * 2 + 1];
                    hp[col + 0] = to_tf32((v1a / (1.f + expf(-v1a))) * v3a * wr);
                    hp[col + 1] = to_tf32((v1b / (1.f + expf(-v1b))) * v3b * wr);
                }
            }
        }
    }
}

// ---------------- kernel 6: GEMM-2 (hmid @ w2^T) + scatter-add ----------------
// 128x128 tile. A via cp.async double-buffer; B via LDG->cvt->STS staging.
__global__ __launch_bounds__(256, 2) void gemm2_kernel(const float* __restrict__ w2,
                                                       float* __restrict__ out) {
    int ti = blockIdx.y;
    if (ti >= g_ntiles) return;
    int e   = g_tile_e[ti];
    int mt  = g_tile_m[ti];
    int cnt = g_cnt[e];
    int off = g_off[e];
    int row0  = off + mt * MT;
    int mrows = cnt - mt * MT; if (mrows > MT) mrows = MT;
    int n0 = blockIdx.x * 128;   // over HID

    __shared__ float As[2][MT][PAD];
    __shared__ float Bs[2][128][PAD];

    int tid = threadIdx.x;
    const float* w2p = w2 + ((size_t)e * HID + n0) * FFN;

    // warp tiling: 4 m-warps x 2 n-warps, warp tile 32m x 64n
    int wid = tid >> 5, lane = tid & 31;
    int wm = (wid & 3) * 32;
    int wn = (wid >> 2) * 64;
    int lr = lane >> 2, lc = lane & 3;

    float cc[2][8][4];
#pragma unroll
    for (int i = 0; i < 2; i++)
#pragma unroll
        for (int j = 0; j < 8; j++)
#pragma unroll
            for (int q = 0; q < 4; q++) cc[i][j][q] = 0.f;

    float4 sb[2];  // B staging: 128x16 / 256 threads = 2 float4

    auto loadA = [&](int buf, int k0) {
#pragma unroll
        for (int j = 0; j < 2; j++) {
            int idx = 2 * tid + j;
            int row = idx >> 2;
            int c4  = idx & 3;
            bool p = row < mrows;
            const float* src = g_hmid + (size_t)(row0 + (p ? row : 0)) * FFN + k0 + c4 * 4;
            uint32_t sa = (uint32_t)__cvta_generic_to_shared(&As[buf][row][c4 * 4]);
            cp_async16(sa, src, p ? 16 : 0);
        }
    };
    auto ldgB = [&](int k0) {
#pragma unroll
        for (int q = 0; q < 2; q++) {
            int idx = tid + q * 256;
            int row = idx >> 2;
            int c4  = idx & 3;
            sb[q] = *(const float4*)(w2p + (size_t)row * FFN + k0 + c4 * 4);
        }
    };
    auto stsB = [&](int buf) {
#pragma unroll
        for (int q = 0; q < 2; q++) {
            int idx = tid + q * 256;
            int row = idx >> 2;
            int c4  = idx & 3;
            float4 t;
            t.x = to_tf32(sb[q].x); t.y = to_tf32(sb[q].y);
            t.z = to_tf32(sb[q].z); t.w = to_tf32(sb[q].w);
            *(float4*)(&Bs[buf][row][c4 * 4]) = t;
        }
    };

    const int nk = FFN / BK;   // 448

    loadA(0, 0); CP_COMMIT();
    ldgB(0);
    stsB(0);
    loadA(1, BK); CP_COMMIT();
    ldgB(BK);
    CP_WAIT(1);
    __syncthreads();

    for (int i = 0; i < nk; i++) {
        int cur = i & 1, nxt = cur ^ 1;
#pragma unroll
        for (int kk = 0; kk < BK; kk += 8) {
            unsigned a[2][4], b[8][2];
#pragma unroll
            for (int sm = 0; sm < 2; sm++) {
                int arr = wm + sm * 16 + lr;
                a[sm][0] = __float_as_uint(As[cur][arr][kk + lc]);
                a[sm][1] = __float_as_uint(As[cur][arr + 8][kk + lc]);
                a[sm][2] = __float_as_uint(As[cur][arr][kk + 4 + lc]);
                a[sm][3] = __float_as_uint(As[cur][arr + 8][kk + 4 + lc]);
            }
#pragma unroll
            for (int sn = 0; sn < 8; sn++) {
                int br = wn + sn * 8 + lr;
                b[sn][0] = __float_as_uint(Bs[cur][br][kk + lc]);
                b[sn][1] = __float_as_uint(Bs[cur][br][kk + 4 + lc]);
            }
#pragma unroll
            for (int sm = 0; sm < 2; sm++)
#pragma unroll
                for (int sn = 0; sn < 8; sn++)
                    mma_tf32(cc[sm][sn], a[sm], b[sn]);
        }
        __syncthreads();
        if (i + 1 < nk) {
            stsB(nxt);
            if (i + 2 < nk) {
                ldgB((i + 2) * BK);
                loadA(cur, (i + 2) * BK); CP_COMMIT();
                CP_WAIT(1);
            } else {
                CP_WAIT(0);
            }
            __syncthreads();
        }
    }

    // epilogue: atomic scatter-add into out[token][h]
#pragma unroll
    for (int sm = 0; sm < 2; sm++) {
        int rbase = wm + sm * 16 + lr;
#pragma unroll
        for (int half = 0; half < 2; half++) {
            int r = rbase + half * 8;
            if (r < mrows) {
                int tok = g_ptok[row0 + r];
                float* op = out + (size_t)tok * HID + n0;
#pragma unroll
                for (int sn = 0; sn < 8; sn++) {
                    int col = wn + sn * 8 + lc * 2;
                    atomicAdd(&op[col + 0], cc[sm][sn][half * 2 + 0]);
                    atomicAdd(&op[col + 1], cc[sm][sn][half * 2 + 1]);
                }
            }
        }
    }
}

// ---------------- host launch ----------------
extern "C" void kernel_launch(void* const* d_in, const int* in_sizes, int n_in,
                              void* d_out, int out_size) {
    const float* x      = (const float*)d_in[0];
    const float* gate   = (const float*)d_in[1];
    const float* w1     = (const float*)d_in[2];
    const float* w3     = (const float*)d_in[3];
    const float* w2     = (const float*)d_in[4];
    const float* scales = (const float*)d_in[5];

    float* out = (float*)d_out;
    int write_logits = ((size_t)out_size >= OUT_ELEMS + (size_t)TOK * NE) ? 1 : 0;
    float* logits = out + OUT_ELEMS;

    init_kernel<<<2048, 256>>>((float4*)out);
    router_kernel<<<TOK / 64, 256>>>(x, gate, logits, write_logits);
    scan_kernel<<<1, 32>>>();
    scatter_kernel<<<TOK / 256, 256>>>();
    gather_kernel<<<NPAIR, 128>>>(x, scales);

    dim3 g1(FFN / 64, MAXT);
    gemm1_kernel<<<g1, 256>>>(w1, w3);

    dim3 g2(HID / 128, MAXT);
    gemm2_kernel<<<g2, 256>>>(w2, out);
}

// round 5
// speedup vs baseline: 1.6595x; 1.0510x over previous
#include <cuda_runtime.h>
#include <cstdint>
#include <math.h>

// ---------------- problem constants ----------------
#define TOK      8192
#define HID      2048
#define FFN      7168
#define NE       8
#define NPAIR    (TOK * 2)
#define OUT_ELEMS ((size_t)TOK * HID)
#define MT       256            // GEMM m-tile rows
#define MAXT     72             // 16384/256 + NE
#define WELEM    ((size_t)NE * FFN * HID)   // per weight tensor: 117440512

// ---------------- device scratch ----------------
__device__ int   g_cnt[NE];
__device__ int   g_off[NE];
__device__ int   g_cur[NE];
__device__ int   g_ntiles;
__device__ int   g_tile_e[MAXT];
__device__ int   g_tile_m[MAXT];
__device__ int   g_sel[NPAIR];
__device__ float g_selw[NPAIR];
__device__ int   g_ptok[NPAIR];
__device__ float g_pw[NPAIR];
__device__ int   g_pe[NPAIR];
__device__ float g_logit_dump[TOK * NE];
__device__ float g_xg[(size_t)NPAIR * HID];     // scaled activations, tf32-rounded
__device__ float g_hmid[(size_t)NPAIR * FFN];   // silu(xw1)*(xw3)*wr, tf32-rounded
__device__ float g_w1r[WELEM];                  // tf32-rounded weights
__device__ float g_w3r[WELEM];
__device__ float g_w2r[WELEM];

// ---------------- helpers ----------------
__device__ __forceinline__ float to_tf32(float x) {
    unsigned u;
    asm("cvt.rna.tf32.f32 %0, %1;" : "=r"(u) : "f"(x));
    return __uint_as_float(u);
}

__device__ __forceinline__ void mma_tf32(float c[4], const unsigned a[4], const unsigned b[2]) {
    asm volatile(
        "mma.sync.aligned.m16n8k8.row.col.f32.tf32.tf32.f32 "
        "{%0,%1,%2,%3}, {%4,%5,%6,%7}, {%8,%9}, {%0,%1,%2,%3};\n"
        : "+f"(c[0]), "+f"(c[1]), "+f"(c[2]), "+f"(c[3])
        : "r"(a[0]), "r"(a[1]), "r"(a[2]), "r"(a[3]), "r"(b[0]), "r"(b[1]));
}

__device__ __forceinline__ void cp_async16(uint32_t saddr, const void* gptr, int szbytes) {
    asm volatile("cp.async.cg.shared.global [%0], [%1], 16, %2;\n"
                 :: "r"(saddr), "l"(gptr), "r"(szbytes));
}
#define CP_COMMIT() asm volatile("cp.async.commit_group;\n" ::)
#define CP_WAIT(n)  asm volatile("cp.async.wait_group %0;\n" :: "n"(n))

// ---------------- kernel 0: zero output + counters ----------------
__global__ void init_kernel(float4* out4) {
    size_t i      = (size_t)blockIdx.x * blockDim.x + threadIdx.x;
    size_t stride = (size_t)gridDim.x * blockDim.x;
    const size_t n4 = OUT_ELEMS / 4;
    float4 z = make_float4(0.f, 0.f, 0.f, 0.f);
    for (size_t j = i; j < n4; j += stride) out4[j] = z;
    if (blockIdx.x == 0 && threadIdx.x < NE) g_cnt[threadIdx.x] = 0;
}

// ---------------- kernel 0b: round weights to tf32 (once per launch) ----------------
__global__ void round_weights(const float4* __restrict__ src, float4* __restrict__ dst) {
    size_t i      = (size_t)blockIdx.x * blockDim.x + threadIdx.x;
    size_t stride = (size_t)gridDim.x * blockDim.x;
    const size_t n4 = WELEM / 4;
    for (size_t j = i; j < n4; j += stride) {
        float4 v = src[j];
        float4 o;
        o.x = to_tf32(v.x); o.y = to_tf32(v.y);
        o.z = to_tf32(v.z); o.w = to_tf32(v.w);
        dst[j] = o;
    }
}

// ---------------- kernel 1: router ----------------
__global__ void router_kernel(const float* __restrict__ x,
                              const float* __restrict__ gate,
                              float* __restrict__ logits_out,
                              int write_logits) {
    int warp = threadIdx.x >> 5;
    int lane = threadIdx.x & 31;
    int tbase = blockIdx.x * 64 + warp * 8;

    for (int i = 0; i < 8; i++) {
        int t = tbase + i;
        const float4* xp = (const float4*)(x + (size_t)t * HID);
        float acc[NE];
#pragma unroll
        for (int e = 0; e < NE; e++) acc[e] = 0.f;
        for (int c = lane; c < HID / 4; c += 32) {
            float4 xv = __ldg(xp + c);
#pragma unroll
            for (int e = 0; e < NE; e++) {
                float4 gv = __ldg((const float4*)(gate + (size_t)e * HID) + c);
                acc[e] += xv.x * gv.x + xv.y * gv.y + xv.z * gv.z + xv.w * gv.w;
            }
        }
#pragma unroll
        for (int e = 0; e < NE; e++)
            for (int o = 16; o; o >>= 1) acc[e] += __shfl_xor_sync(0xffffffffu, acc[e], o);

        if (lane == 0) {
            float* lo = write_logits ? logits_out : g_logit_dump;
#pragma unroll
            for (int e = 0; e < NE; e++) lo[(size_t)t * NE + e] = acc[e];
            int e0 = 0;
            for (int e = 1; e < NE; e++) if (acc[e] > acc[e0]) e0 = e;
            int e1 = -1;
            for (int e = 0; e < NE; e++) {
                if (e == e0) continue;
                if (e1 < 0 || acc[e] > acc[e1]) e1 = e;
            }
            float w0 = 1.f / (1.f + expf(acc[e1] - acc[e0]));
            float w1 = 1.f - w0;
            g_sel[t * 2 + 0] = e0; g_selw[t * 2 + 0] = w0;
            g_sel[t * 2 + 1] = e1; g_selw[t * 2 + 1] = w1;
            atomicAdd(&g_cnt[e0], 1);
            atomicAdd(&g_cnt[e1], 1);
        }
    }
}

// ---------------- kernel 2: scan + tile list ----------------
__global__ void scan_kernel() {
    if (threadIdx.x == 0) {
        int o = 0, nt = 0;
        for (int e = 0; e < NE; e++) {
            g_off[e] = o;
            g_cur[e] = o;
            int c = g_cnt[e];
            int tl = (c + MT - 1) / MT;
            for (int m = 0; m < tl; m++) { g_tile_e[nt] = e; g_tile_m[nt] = m; nt++; }
            o += c;
        }
        g_ntiles = nt;
    }
}

// ---------------- kernel 3: scatter ----------------
__global__ void scatter_kernel() {
    int t = blockIdx.x * blockDim.x + threadIdx.x;
    if (t >= TOK) return;
#pragma unroll
    for (int k = 0; k < 2; k++) {
        int e = g_sel[t * 2 + k];
        int pos = atomicAdd(&g_cur[e], 1);
        g_ptok[pos] = t;
        g_pw[pos]   = g_selw[t * 2 + k];
        g_pe[pos]   = e;
    }
}

// ---------------- kernel 4: gather + scale divide (tf32-rounded) ----------------
__global__ void gather_kernel(const float* __restrict__ x,
                              const float* __restrict__ scales) {
    int r = blockIdx.x;
    int tok = g_ptok[r];
    int e   = g_pe[r];
    const float4* xp = (const float4*)(x + (size_t)tok * HID);
    const float4* sp = (const float4*)(scales + (size_t)e * HID);
    float4* dp = (float4*)(g_xg + (size_t)r * HID);
    for (int c = threadIdx.x; c < HID / 4; c += blockDim.x) {
        float4 xv = xp[c], sv = sp[c];
        float4 o;
        o.x = to_tf32(xv.x / sv.x); o.y = to_tf32(xv.y / sv.y);
        o.z = to_tf32(xv.z / sv.z); o.w = to_tf32(xv.w / sv.w);
        dp[c] = o;
    }
}

// ================== GEMM config ==================
#define BK      16
#define PADF    20                       // floats per smem row (80B, conflict-free)
#define STAGES  4
#define A_F     (MT * PADF)              // 5120 floats per A stage
#define STAGE_F 6400                     // A(5120) + B(1280)
#define SMEM_DYN (STAGES * STAGE_F * 4)  // 102400 B

// ---------------- kernel 5: GEMM-1: hmid = silu(xg@w1^T)*(xg@w3^T)*wr ----------------
// tile M=256, N=32 (w1) + 32 (w3). 8 warps: 4 m-warps x 2 n-warps; warp tile 64m x 16n/matrix.
__global__ __launch_bounds__(256, 2) void gemm1_kernel(void) {
    int ti = blockIdx.y;
    if (ti >= g_ntiles) return;
    int e    = g_tile_e[ti];
    int mt   = g_tile_m[ti];
    int cnt  = g_cnt[e];
    int off  = g_off[e];
    int row0 = off + mt * MT;
    int mrows = cnt - mt * MT; if (mrows > MT) mrows = MT;
    int n0 = blockIdx.x * 32;

    extern __shared__ float sm[];
    uint32_t smb = (uint32_t)__cvta_generic_to_shared(sm);

    int tid  = threadIdx.x;
    int wid  = tid >> 5, lane = tid & 31;
    int wm   = (wid & 3) * 64;
    int wn   = (wid >> 2) * 16;
    int lr   = lane >> 2, lc = lane & 3;

    const float* w1p = g_w1r + ((size_t)e * FFN + n0) * HID;
    const float* w3p = g_w3r + ((size_t)e * FFN + n0) * HID;

    // A: 1024 float4 per stage -> 4 per thread. B: 256 float4 -> 1 per thread.
    int bmat = tid >> 7;           // 0 -> w1, 1 -> w3
    int bidx = tid & 127;
    int brow = bidx >> 2, bc4 = bidx & 3;
    const float* bsrc = (bmat == 0 ? w1p : w3p) + (size_t)brow * HID + bc4 * 4;
    uint32_t bdst_off = (uint32_t)((5120 + bmat * 640 + brow * PADF + bc4 * 4) * 4);

    float c1[4][2][4], c2[4][2][4];
#pragma unroll
    for (int i = 0; i < 4; i++)
#pragma unroll
        for (int j = 0; j < 2; j++)
#pragma unroll
            for (int q = 0; q < 4; q++) { c1[i][j][q] = 0.f; c2[i][j][q] = 0.f; }

    auto load_stage = [&](int st, int k0) {
        uint32_t sb = smb + (uint32_t)(st * STAGE_F * 4);
#pragma unroll
        for (int j = 0; j < 4; j++) {
            int idx = j * 256 + tid;
            int row = idx >> 2, c4 = idx & 3;
            int p = (row < mrows) ? 16 : 0;
            cp_async16(sb + (uint32_t)((row * PADF + c4 * 4) * 4),
                       g_xg + (size_t)(row0 + row) * HID + k0 + c4 * 4, p);
        }
        cp_async16(sb + bdst_off, bsrc + k0, 16);
    };

    const int nk = HID / BK;   // 128
    load_stage(0, 0);      CP_COMMIT();
    load_stage(1, BK);     CP_COMMIT();
    load_stage(2, 2 * BK); CP_COMMIT();

    for (int i = 0; i < nk; i++) {
        CP_WAIT(2);
        __syncthreads();
        const float* S  = sm + (i & 3) * STAGE_F;
        const float* B1 = S + 5120;
        const float* B3 = S + 5760;
#pragma unroll
        for (int kk = 0; kk < BK; kk += 8) {
            unsigned a[4][4], b1[2][2], b3[2][2];
#pragma unroll
            for (int s = 0; s < 4; s++) {
                int ar = wm + s * 16 + lr;
                a[s][0] = __float_as_uint(S[ar * PADF + kk + lc]);
                a[s][1] = __float_as_uint(S[(ar + 8) * PADF + kk + lc]);
                a[s][2] = __float_as_uint(S[ar * PADF + kk + 4 + lc]);
                a[s][3] = __float_as_uint(S[(ar + 8) * PADF + kk + 4 + lc]);
            }
#pragma unroll
            for (int sn = 0; sn < 2; sn++) {
                int br = wn + sn * 8 + lr;
                b1[sn][0] = __float_as_uint(B1[br * PADF + kk + lc]);
                b1[sn][1] = __float_as_uint(B1[br * PADF + kk + 4 + lc]);
                b3[sn][0] = __float_as_uint(B3[br * PADF + kk + lc]);
                b3[sn][1] = __float_as_uint(B3[br * PADF + kk + 4 + lc]);
            }
#pragma unroll
            for (int s = 0; s < 4; s++)
#pragma unroll
                for (int sn = 0; sn < 2; sn++) {
                    mma_tf32(c1[s][sn], a[s], b1[sn]);
                    mma_tf32(c2[s][sn], a[s], b3[sn]);
                }
        }
        if (i + 3 < nk) load_stage((i + 3) & 3, (i + 3) * BK);
        CP_COMMIT();
    }

    // epilogue: hmid = silu(c1) * c2 * wr (tf32-rounded)
#pragma unroll
    for (int s = 0; s < 4; s++) {
#pragma unroll
        for (int half = 0; half < 2; half++) {
            int r = wm + s * 16 + half * 8 + lr;
            if (r < mrows) {
                float wr = g_pw[row0 + r];
                float* hp = g_hmid + (size_t)(row0 + r) * FFN + n0;
#pragma unroll
                for (int sn = 0; sn < 2; sn++) {
                    int col = wn + sn * 8 + lc * 2;
                    float v1a = c1[s][sn][half * 2 + 0], v3a = c2[s][sn][half * 2 + 0];
                    float v1b = c1[s][sn][half * 2 + 1], v3b = c2[s][sn][half * 2 + 1];
                    hp[col + 0] = to_tf32((v1a / (1.f + expf(-v1a))) * v3a * wr);
                    hp[col + 1] = to_tf32((v1b / (1.f + expf(-v1b))) * v3b * wr);
                }
            }
        }
    }
}

// ---------------- kernel 6: GEMM-2: out += hmid @ w2^T (scatter-add) ----------------
// tile M=256, N=64. 8 warps: 4 m x 2 n; warp tile 64m x 32n.
__global__ __launch_bounds__(256, 2) void gemm2_kernel(float* __restrict__ out) {
    int ti = blockIdx.y;
    if (ti >= g_ntiles) return;
    int e    = g_tile_e[ti];
    int mt   = g_tile_m[ti];
    int cnt  = g_cnt[e];
    int off  = g_off[e];
    int row0 = off + mt * MT;
    int mrows = cnt - mt * MT; if (mrows > MT) mrows = MT;
    int n0 = blockIdx.x * 64;

    extern __shared__ float sm[];
    uint32_t smb = (uint32_t)__cvta_generic_to_shared(sm);

    int tid  = threadIdx.x;
    int wid  = tid >> 5, lane = tid & 31;
    int wm   = (wid & 3) * 64;
    int wn   = (wid >> 2) * 32;
    int lr   = lane >> 2, lc = lane & 3;

    const float* w2p = g_w2r + ((size_t)e * HID + n0) * FFN;

    int brow = tid >> 2, bc4 = tid & 3;   // 64 rows x 4 f4-cols = 256 f4 -> 1/thread
    const float* bsrc = w2p + (size_t)brow * FFN + bc4 * 4;
    uint32_t bdst_off = (uint32_t)((5120 + brow * PADF + bc4 * 4) * 4);

    float cc[4][4][4];
#pragma unroll
    for (int i = 0; i < 4; i++)
#pragma unroll
        for (int j = 0; j < 4; j++)
#pragma unroll
            for (int q = 0; q < 4; q++) cc[i][j][q] = 0.f;

    auto load_stage = [&](int st, int k0) {
        uint32_t sb = smb + (uint32_t)(st * STAGE_F * 4);
#pragma unroll
        for (int j = 0; j < 4; j++) {
            int idx = j * 256 + tid;
            int row = idx >> 2, c4 = idx & 3;
            int p = (row < mrows) ? 16 : 0;
            cp_async16(sb + (uint32_t)((row * PADF + c4 * 4) * 4),
                       g_hmid + (size_t)(row0 + row) * FFN + k0 + c4 * 4, p);
        }
        cp_async16(sb + bdst_off, bsrc + k0, 16);
    };

    const int nk = FFN / BK;   // 448
    load_stage(0, 0);      CP_COMMIT();
    load_stage(1, BK);     CP_COMMIT();
    load_stage(2, 2 * BK); CP_COMMIT();

    for (int i = 0; i < nk; i++) {
        CP_WAIT(2);
        __syncthreads();
        const float* S = sm + (i & 3) * STAGE_F;
        const float* B = S + 5120;
#pragma unroll
        for (int kk = 0; kk < BK; kk += 8) {
            unsigned a[4][4], b[4][2];
#pragma unroll
            for (int s = 0; s < 4; s++) {
                int ar = wm + s * 16 + lr;
                a[s][0] = __float_as_uint(S[ar * PADF + kk + lc]);
                a[s][1] = __float_as_uint(S[(ar + 8) * PADF + kk + lc]);
                a[s][2] = __float_as_uint(S[ar * PADF + kk + 4 + lc]);
                a[s][3] = __float_as_uint(S[(ar + 8) * PADF + kk + 4 + lc]);
            }
#pragma unroll
            for (int sn = 0; sn < 4; sn++) {
                int br = wn + sn * 8 + lr;
                b[sn][0] = __float_as_uint(B[br * PADF + kk + lc]);
                b[sn][1] = __float_as_uint(B[br * PADF + kk + 4 + lc]);
            }
#pragma unroll
            for (int s = 0; s < 4; s++)
#pragma unroll
                for (int sn = 0; sn < 4; sn++)
                    mma_tf32(cc[s][sn], a[s], b[sn]);
        }
        if (i + 3 < nk) load_stage((i + 3) & 3, (i + 3) * BK);
        CP_COMMIT();
    }

    // epilogue: atomic scatter-add into out[token][h]
#pragma unroll
    for (int s = 0; s < 4; s++) {
#pragma unroll
        for (int half = 0; half < 2; half++) {
            int r = wm + s * 16 + half * 8 + lr;
            if (r < mrows) {
                int tok = g_ptok[row0 + r];
                float* op = out + (size_t)tok * HID + n0;
#pragma unroll
                for (int sn = 0; sn < 4; sn++) {
                    int col = wn + sn * 8 + lc * 2;
                    atomicAdd(&op[col + 0], cc[s][sn][half * 2 + 0]);
                    atomicAdd(&op[col + 1], cc[s][sn][half * 2 + 1]);
                }
            }
        }
    }
}

// ---------------- host launch ----------------
extern "C" void kernel_launch(void* const* d_in, const int* in_sizes, int n_in,
                              void* d_out, int out_size) {
    const float* x      = (const float*)d_in[0];
    const float* gate   = (const float*)d_in[1];
    const float* w1     = (const float*)d_in[2];
    const float* w3     = (const float*)d_in[3];
    const float* w2     = (const float*)d_in[4];
    const float* scales = (const float*)d_in[5];

    float* out = (float*)d_out;
    int write_logits = ((size_t)out_size >= OUT_ELEMS + (size_t)TOK * NE) ? 1 : 0;
    float* logits = out + OUT_ELEMS;

    cudaFuncSetAttribute(gemm1_kernel, cudaFuncAttributeMaxDynamicSharedMemorySize, SMEM_DYN);
    cudaFuncSetAttribute(gemm2_kernel, cudaFuncAttributeMaxDynamicSharedMemorySize, SMEM_DYN);

    float* w1r_p; cudaGetSymbolAddress((void**)&w1r_p, g_w1r);
    float* w3r_p; cudaGetSymbolAddress((void**)&w3r_p, g_w3r);
    float* w2r_p; cudaGetSymbolAddress((void**)&w2r_p, g_w2r);

    init_kernel<<<2048, 256>>>((float4*)out);
    round_weights<<<4096, 256>>>((const float4*)w1, (float4*)w1r_p);
    round_weights<<<4096, 256>>>((const float4*)w3, (float4*)w3r_p);
    round_weights<<<4096, 256>>>((const float4*)w2, (float4*)w2r_p);
    router_kernel<<<TOK / 64, 256>>>(x, gate, logits, write_logits);
    scan_kernel<<<1, 32>>>();
    scatter_kernel<<<TOK / 256, 256>>>();
    gather_kernel<<<NPAIR, 128>>>(x, scales);

    dim3 g1(FFN / 32, MAXT);
    gemm1_kernel<<<g1, 256, SMEM_DYN>>>();

    dim3 g2(HID / 64, MAXT);
    gemm2_kernel<<<g2, 256, SMEM_DYN>>>(out);
}

// round 6
// speedup vs baseline: 1.7731x; 1.0684x over previous
#include <cuda_runtime.h>
#include <cstdint>
#include <math.h>

// ---------------- problem constants ----------------
#define TOK      8192
#define HID      2048
#define FFN      7168
#define NE       8
#define NPAIR    (TOK * 2)
#define OUT_ELEMS ((size_t)TOK * HID)
#define MT       256            // GEMM m-tile rows
#define MAXT     72             // 16384/256 + NE

// ---------------- device scratch ----------------
__device__ int   g_cnt[NE];
__device__ int   g_off[NE];
__device__ int   g_cur[NE];
__device__ int   g_ntiles;
__device__ int   g_tile_e[MAXT];
__device__ int   g_tile_m[MAXT];
__device__ int   g_sel[NPAIR];
__device__ float g_selw[NPAIR];
__device__ int   g_ptok[NPAIR];
__device__ float g_pw[NPAIR];
__device__ int   g_pe[NPAIR];
__device__ float g_logit_dump[TOK * NE];
__device__ float g_xg[(size_t)NPAIR * HID];     // scaled activations, tf32-rounded
__device__ float g_hmid[(size_t)NPAIR * FFN];   // silu(xw1)*(xw3)*wr, tf32-rounded

// ---------------- helpers ----------------
__device__ __forceinline__ float to_tf32(float x) {
    unsigned u;
    asm("cvt.rna.tf32.f32 %0, %1;" : "=r"(u) : "f"(x));
    return __uint_as_float(u);
}

__device__ __forceinline__ void mma_tf32(float c[4], const unsigned a[4], const unsigned b[2]) {
    asm volatile(
        "mma.sync.aligned.m16n8k8.row.col.f32.tf32.tf32.f32 "
        "{%0,%1,%2,%3}, {%4,%5,%6,%7}, {%8,%9}, {%0,%1,%2,%3};\n"
        : "+f"(c[0]), "+f"(c[1]), "+f"(c[2]), "+f"(c[3])
        : "r"(a[0]), "r"(a[1]), "r"(a[2]), "r"(a[3]), "r"(b[0]), "r"(b[1]));
}

__device__ __forceinline__ void cp_async16(uint32_t saddr, const void* gptr, int szbytes) {
    asm volatile("cp.async.cg.shared.global [%0], [%1], 16, %2;\n"
                 :: "r"(saddr), "l"(gptr), "r"(szbytes));
}
#define CP_COMMIT() asm volatile("cp.async.commit_group;\n" ::)
#define CP_WAIT(n)  asm volatile("cp.async.wait_group %0;\n" :: "n"(n))

#define STS128F(addr, a, b, c, d) \
    asm volatile("st.shared.v4.f32 [%0], {%1, %2, %3, %4};" \
                 :: "r"(addr), "f"(a), "f"(b), "f"(c), "f"(d) : "memory")

// ---------------- kernel 0: zero output + counters ----------------
__global__ void init_kernel(float4* out4) {
    size_t i      = (size_t)blockIdx.x * blockDim.x + threadIdx.x;
    size_t stride = (size_t)gridDim.x * blockDim.x;
    const size_t n4 = OUT_ELEMS / 4;
    float4 z = make_float4(0.f, 0.f, 0.f, 0.f);
    for (size_t j = i; j < n4; j += stride) out4[j] = z;
    if (blockIdx.x == 0 && threadIdx.x < NE) g_cnt[threadIdx.x] = 0;
}

// ---------------- kernel 1: router ----------------
__global__ void router_kernel(const float* __restrict__ x,
                              const float* __restrict__ gate,
                              float* __restrict__ logits_out,
                              int write_logits) {
    int warp = threadIdx.x >> 5;
    int lane = threadIdx.x & 31;
    int tbase = blockIdx.x * 64 + warp * 8;

    for (int i = 0; i < 8; i++) {
        int t = tbase + i;
        const float4* xp = (const float4*)(x + (size_t)t * HID);
        float acc[NE];
#pragma unroll
        for (int e = 0; e < NE; e++) acc[e] = 0.f;
        for (int c = lane; c < HID / 4; c += 32) {
            float4 xv = __ldg(xp + c);
#pragma unroll
            for (int e = 0; e < NE; e++) {
                float4 gv = __ldg((const float4*)(gate + (size_t)e * HID) + c);
                acc[e] += xv.x * gv.x + xv.y * gv.y + xv.z * gv.z + xv.w * gv.w;
            }
        }
#pragma unroll
        for (int e = 0; e < NE; e++)
            for (int o = 16; o; o >>= 1) acc[e] += __shfl_xor_sync(0xffffffffu, acc[e], o);

        if (lane == 0) {
            float* lo = write_logits ? logits_out : g_logit_dump;
#pragma unroll
            for (int e = 0; e < NE; e++) lo[(size_t)t * NE + e] = acc[e];
            int e0 = 0;
            for (int e = 1; e < NE; e++) if (acc[e] > acc[e0]) e0 = e;
            int e1 = -1;
            for (int e = 0; e < NE; e++) {
                if (e == e0) continue;
                if (e1 < 0 || acc[e] > acc[e1]) e1 = e;
            }
            float w0 = 1.f / (1.f + expf(acc[e1] - acc[e0]));
            float w1 = 1.f - w0;
            g_sel[t * 2 + 0] = e0; g_selw[t * 2 + 0] = w0;
            g_sel[t * 2 + 1] = e1; g_selw[t * 2 + 1] = w1;
            atomicAdd(&g_cnt[e0], 1);
            atomicAdd(&g_cnt[e1], 1);
        }
    }
}

// ---------------- kernel 2: scan + tile list ----------------
__global__ void scan_kernel() {
    if (threadIdx.x == 0) {
        int o = 0, nt = 0;
        for (int e = 0; e < NE; e++) {
            g_off[e] = o;
            g_cur[e] = o;
            int c = g_cnt[e];
            int tl = (c + MT - 1) / MT;
            for (int m = 0; m < tl; m++) { g_tile_e[nt] = e; g_tile_m[nt] = m; nt++; }
            o += c;
        }
        g_ntiles = nt;
    }
}

// ---------------- kernel 3: scatter ----------------
__global__ void scatter_kernel() {
    int t = blockIdx.x * blockDim.x + threadIdx.x;
    if (t >= TOK) return;
#pragma unroll
    for (int k = 0; k < 2; k++) {
        int e = g_sel[t * 2 + k];
        int pos = atomicAdd(&g_cur[e], 1);
        g_ptok[pos] = t;
        g_pw[pos]   = g_selw[t * 2 + k];
        g_pe[pos]   = e;
    }
}

// ---------------- kernel 4: gather + scale divide (tf32-rounded) ----------------
__global__ void gather_kernel(const float* __restrict__ x,
                              const float* __restrict__ scales) {
    int r = blockIdx.x;
    int tok = g_ptok[r];
    int e   = g_pe[r];
    const float4* xp = (const float4*)(x + (size_t)tok * HID);
    const float4* sp = (const float4*)(scales + (size_t)e * HID);
    float4* dp = (float4*)(g_xg + (size_t)r * HID);
    for (int c = threadIdx.x; c < HID / 4; c += blockDim.x) {
        float4 xv = xp[c], sv = sp[c];
        float4 o;
        o.x = to_tf32(xv.x / sv.x); o.y = to_tf32(xv.y / sv.y);
        o.z = to_tf32(xv.z / sv.z); o.w = to_tf32(xv.w / sv.w);
        dp[c] = o;
    }
}

// ================== GEMM config ==================
#define BK      16
#define PADF    20                       // floats per smem row (80B, conflict-free)
#define STAGES  4
#define A_STF   (MT * PADF)              // 5120 floats per A stage
#define A_TOTF  (STAGES * A_STF)         // 20480 floats
#define B_ROWS  128                      // B rows per tile (both GEMMs)
#define B_STF   (B_ROWS * PADF)          // 2560 floats per B buffer
#define SMEM_DYN ((A_TOTF + 2 * B_STF) * 4)   // 102400 B

// ---------------- kernel 5: GEMM-1: hmid = silu(xg@w1^T)*(xg@w3^T)*wr ----------------
// tile M=256, N=64 per matrix (128 B rows). 16 warps: 4 m x 4 n; warp 64m x 16n/matrix.
// A: 4-stage cp.async from pre-rounded g_xg. B: LDG(raw w1/w3) -> cvt.rna.tf32 -> STS, 2 bufs.
__global__ __launch_bounds__(512, 1) void gemm1_kernel(const float* __restrict__ w1,
                                                       const float* __restrict__ w3) {
    int ti = blockIdx.y;
    if (ti >= g_ntiles) return;
    int e    = g_tile_e[ti];
    int mt   = g_tile_m[ti];
    int cnt  = g_cnt[e];
    int off  = g_off[e];
    int row0 = off + mt * MT;
    int mrows = cnt - mt * MT; if (mrows > MT) mrows = MT;
    int n0 = blockIdx.x * 64;

    extern __shared__ float sm[];
    uint32_t smb = (uint32_t)__cvta_generic_to_shared(sm);
    float* Bsm = sm + A_TOTF;

    int tid  = threadIdx.x;
    int wid  = tid >> 5, lane = tid & 31;
    int wm   = (wid & 3) * 64;
    int wn   = (wid >> 2) * 16;
    int lr   = lane >> 2, lc = lane & 3;

    const float* w1p = w1 + ((size_t)e * FFN + n0) * HID;
    const float* w3p = w3 + ((size_t)e * FFN + n0) * HID;

    // B: 128 rows x 4 f4-cols = 512 float4 -> 1 per thread
    int brow = tid >> 2, bc4 = tid & 3;
    const float* bsrc = ((brow < 64) ? (w1p + (size_t)brow * HID)
                                     : (w3p + (size_t)(brow - 64) * HID)) + bc4 * 4;
    uint32_t bdst = smb + (uint32_t)((A_TOTF + brow * PADF + bc4 * 4) * 4);

    float c1[4][2][4], c2[4][2][4];
#pragma unroll
    for (int i = 0; i < 4; i++)
#pragma unroll
        for (int j = 0; j < 2; j++)
#pragma unroll
            for (int q = 0; q < 4; q++) { c1[i][j][q] = 0.f; c2[i][j][q] = 0.f; }

    auto loadA = [&](int st, int k0) {
        uint32_t sb = smb + (uint32_t)(st * A_STF * 4);
#pragma unroll
        for (int j = 0; j < 2; j++) {
            int idx = j * 512 + tid;
            int row = idx >> 2, c4 = idx & 3;
            int p = (row < mrows) ? 16 : 0;
            cp_async16(sb + (uint32_t)((row * PADF + c4 * 4) * 4),
                       g_xg + (size_t)(row0 + row) * HID + k0 + c4 * 4, p);
        }
    };

    float4 rb;
    const int nk = HID / BK;   // 128

    rb = *(const float4*)(bsrc);
    loadA(0, 0);      CP_COMMIT();
    loadA(1, BK);     CP_COMMIT();
    loadA(2, 2 * BK); CP_COMMIT();
    STS128F(bdst, to_tf32(rb.x), to_tf32(rb.y), to_tf32(rb.z), to_tf32(rb.w));
    rb = *(const float4*)(bsrc + BK);

    for (int i = 0; i < nk; i++) {
        CP_WAIT(2);
        __syncthreads();
        const float* S  = sm + (i & 3) * A_STF;
        const float* B1 = Bsm + (i & 1) * B_STF;
        const float* B3 = B1 + 64 * PADF;
#pragma unroll
        for (int kk = 0; kk < BK; kk += 8) {
            unsigned a[4][4], b1[2][2], b3[2][2];
#pragma unroll
            for (int s = 0; s < 4; s++) {
                int ar = wm + s * 16 + lr;
                a[s][0] = __float_as_uint(S[ar * PADF + kk + lc]);
                a[s][1] = __float_as_uint(S[(ar + 8) * PADF + kk + lc]);
                a[s][2] = __float_as_uint(S[ar * PADF + kk + 4 + lc]);
                a[s][3] = __float_as_uint(S[(ar + 8) * PADF + kk + 4 + lc]);
            }
#pragma unroll
            for (int sn = 0; sn < 2; sn++) {
                int br = wn + sn * 8 + lr;
                b1[sn][0] = __float_as_uint(B1[br * PADF + kk + lc]);
                b1[sn][1] = __float_as_uint(B1[br * PADF + kk + 4 + lc]);
                b3[sn][0] = __float_as_uint(B3[br * PADF + kk + lc]);
                b3[sn][1] = __float_as_uint(B3[br * PADF + kk + 4 + lc]);
            }
#pragma unroll
            for (int s = 0; s < 4; s++)
#pragma unroll
                for (int sn = 0; sn < 2; sn++) {
                    mma_tf32(c1[s][sn], a[s], b1[sn]);
                    mma_tf32(c2[s][sn], a[s], b3[sn]);
                }
        }
        if (i + 1 < nk) {
            uint32_t bd = bdst + (uint32_t)(((i + 1) & 1) * B_STF * 4);
            STS128F(bd, to_tf32(rb.x), to_tf32(rb.y), to_tf32(rb.z), to_tf32(rb.w));
            if (i + 2 < nk) rb = *(const float4*)(bsrc + (i + 2) * BK);
        }
        if (i + 3 < nk) loadA((i + 3) & 3, (i + 3) * BK);
        CP_COMMIT();
    }

    // epilogue: hmid = silu(c1) * c2 * wr (tf32-rounded)
#pragma unroll
    for (int s = 0; s < 4; s++) {
#pragma unroll
        for (int half = 0; half < 2; half++) {
            int r = wm + s * 16 + half * 8 + lr;
            if (r < mrows) {
                float wr = g_pw[row0 + r];
                float* hp = g_hmid + (size_t)(row0 + r) * FFN + n0;
#pragma unroll
                for (int sn = 0; sn < 2; sn++) {
                    int col = wn + sn * 8 + lc * 2;
                    float v1a = c1[s][sn][half * 2 + 0], v3a = c2[s][sn][half * 2 + 0];
                    float v1b = c1[s][sn][half * 2 + 1], v3b = c2[s][sn][half * 2 + 1];
                    hp[col + 0] = to_tf32((v1a / (1.f + expf(-v1a))) * v3a * wr);
                    hp[col + 1] = to_tf32((v1b / (1.f + expf(-v1b))) * v3b * wr);
                }
            }
        }
    }
}

// ---------------- kernel 6: GEMM-2: out += hmid @ w2^T (scatter-add) ----------------
// tile M=256, N=128. 16 warps: 4 m x 4 n; warp 64m x 32n.
__global__ __launch_bounds__(512, 1) void gemm2_kernel(const float* __restrict__ w2,
                                                       float* __restrict__ out) {
    int ti = blockIdx.y;
    if (ti >= g_ntiles) return;
    int e    = g_tile_e[ti];
    int mt   = g_tile_m[ti];
    int cnt  = g_cnt[e];
    int off  = g_off[e];
    int row0 = off + mt * MT;
    int mrows = cnt - mt * MT; if (mrows > MT) mrows = MT;
    int n0 = blockIdx.x * 128;

    extern __shared__ float sm[];
    uint32_t smb = (uint32_t)__cvta_generic_to_shared(sm);
    float* Bsm = sm + A_TOTF;

    int tid  = threadIdx.x;
    int wid  = tid >> 5, lane = tid & 31;
    int wm   = (wid & 3) * 64;
    int wn   = (wid >> 2) * 32;
    int lr   = lane >> 2, lc = lane & 3;

    const float* w2p = w2 + ((size_t)e * HID + n0) * FFN;

    int brow = tid >> 2, bc4 = tid & 3;
    const float* bsrc = w2p + (size_t)brow * FFN + bc4 * 4;
    uint32_t bdst = smb + (uint32_t)((A_TOTF + brow * PADF + bc4 * 4) * 4);

    float cc[4][4][4];
#pragma unroll
    for (int i = 0; i < 4; i++)
#pragma unroll
        for (int j = 0; j < 4; j++)
#pragma unroll
            for (int q = 0; q < 4; q++) cc[i][j][q] = 0.f;

    auto loadA = [&](int st, int k0) {
        uint32_t sb = smb + (uint32_t)(st * A_STF * 4);
#pragma unroll
        for (int j = 0; j < 2; j++) {
            int idx = j * 512 + tid;
            int row = idx >> 2, c4 = idx & 3;
            int p = (row < mrows) ? 16 : 0;
            cp_async16(sb + (uint32_t)((row * PADF + c4 * 4) * 4),
                       g_hmid + (size_t)(row0 + row) * FFN + k0 + c4 * 4, p);
        }
    };

    float4 rb;
    const int nk = FFN / BK;   // 448

    rb = *(const float4*)(bsrc);
    loadA(0, 0);      CP_COMMIT();
    loadA(1, BK);     CP_COMMIT();
    loadA(2, 2 * BK); CP_COMMIT();
    STS128F(bdst, to_tf32(rb.x), to_tf32(rb.y), to_tf32(rb.z), to_tf32(rb.w));
    rb = *(const float4*)(bsrc + BK);

    for (int i = 0; i < nk; i++) {
        CP_WAIT(2);
        __syncthreads();
        const float* S = sm + (i & 3) * A_STF;
        const float* B = Bsm + (i & 1) * B_STF;
#pragma unroll
        for (int kk = 0; kk < BK; kk += 8) {
            unsigned a[4][4], b[4][2];
#pragma unroll
            for (int s = 0; s < 4; s++) {
                int ar = wm + s * 16 + lr;
                a[s][0] = __float_as_uint(S[ar * PADF + kk + lc]);
                a[s][1] = __float_as_uint(S[(ar + 8) * PADF + kk + lc]);
                a[s][2] = __float_as_uint(S[ar * PADF + kk + 4 + lc]);
                a[s][3] = __float_as_uint(S[(ar + 8) * PADF + kk + 4 + lc]);
            }
#pragma unroll
            for (int sn = 0; sn < 4; sn++) {
                int br = wn + sn * 8 + lr;
                b[sn][0] = __float_as_uint(B[br * PADF + kk + lc]);
                b[sn][1] = __float_as_uint(B[br * PADF + kk + 4 + lc]);
            }
#pragma unroll
            for (int s = 0; s < 4; s++)
#pragma unroll
                for (int sn = 0; sn < 4; sn++)
                    mma_tf32(cc[s][sn], a[s], b[sn]);
        }
        if (i + 1 < nk) {
            uint32_t bd = bdst + (uint32_t)(((i + 1) & 1) * B_STF * 4);
            STS128F(bd, to_tf32(rb.x), to_tf32(rb.y), to_tf32(rb.z), to_tf32(rb.w));
            if (i + 2 < nk) rb = *(const float4*)(bsrc + (i + 2) * BK);
        }
        if (i + 3 < nk) loadA((i + 3) & 3, (i + 3) * BK);
        CP_COMMIT();
    }

    // epilogue: atomic scatter-add into out[token][h]
#pragma unroll
    for (int s = 0; s < 4; s++) {
#pragma unroll
        for (int half = 0; half < 2; half++) {
            int r = wm + s * 16 + half * 8 + lr;
            if (r < mrows) {
                int tok = g_ptok[row0 + r];
                float* op = out + (size_t)tok * HID + n0;
#pragma unroll
                for (int sn = 0; sn < 4; sn++) {
                    int col = wn + sn * 8 + lc * 2;
                    atomicAdd(&op[col + 0], cc[s][sn][half * 2 + 0]);
                    atomicAdd(&op[col + 1], cc[s][sn][half * 2 + 1]);
                }
            }
        }
    }
}

// ---------------- host launch ----------------
extern "C" void kernel_launch(void* const* d_in, const int* in_sizes, int n_in,
                              void* d_out, int out_size) {
    const float* x      = (const float*)d_in[0];
    const float* gate   = (const float*)d_in[1];
    const float* w1     = (const float*)d_in[2];
    const float* w3     = (const float*)d_in[3];
    const float* w2     = (const float*)d_in[4];
    const float* scales = (const float*)d_in[5];

    float* out = (float*)d_out;
    int write_logits = ((size_t)out_size >= OUT_ELEMS + (size_t)TOK * NE) ? 1 : 0;
    float* logits = out + OUT_ELEMS;

    cudaFuncSetAttribute(gemm1_kernel, cudaFuncAttributeMaxDynamicSharedMemorySize, SMEM_DYN);
    cudaFuncSetAttribute(gemm2_kernel, cudaFuncAttributeMaxDynamicSharedMemorySize, SMEM_DYN);

    init_kernel<<<2048, 256>>>((float4*)out);
    router_kernel<<<TOK / 64, 256>>>(x, gate, logits, write_logits);
    scan_kernel<<<1, 32>>>();
    scatter_kernel<<<TOK / 256, 256>>>();
    gather_kernel<<<NPAIR, 128>>>(x, scales);

    dim3 g1(FFN / 64, MAXT);
    gemm1_kernel<<<g1, 512, SMEM_DYN>>>(w1, w3);

    dim3 g2(HID / 128, MAXT);
    gemm2_kernel<<<g2, 512, SMEM_DYN>>>(w2, out);
}

// round 7
// speedup vs baseline: 3.2213x; 1.8168x over previous
#include <cuda_runtime.h>
#include <cuda_fp16.h>
#include <cstdint>
#include <math.h>

// ---------------- problem constants ----------------
#define TOK      8192
#define HID      2048
#define FFN      7168
#define NE       8
#define NPAIR    (TOK * 2)
#define OUT_ELEMS ((size_t)TOK * HID)
#define MT       256            // GEMM m-tile rows
#define MAXT     72             // 16384/256 + NE

// ---------------- device scratch ----------------
__device__ int    g_cnt[NE];
__device__ int    g_off[NE];
__device__ int    g_cur[NE];
__device__ int    g_ntiles;
__device__ int    g_tile_e[MAXT];
__device__ int    g_tile_m[MAXT];
__device__ int    g_sel[NPAIR];
__device__ float  g_selw[NPAIR];
__device__ int    g_ptok[NPAIR];
__device__ float  g_pw[NPAIR];
__device__ int    g_pe[NPAIR];
__device__ float  g_logit_dump[TOK * NE];
__device__ __half g_xg[(size_t)NPAIR * HID];    // scaled activations, fp16
__device__ __half g_hmid[(size_t)NPAIR * FFN];  // silu(xw1)*(xw3)*wr, fp16

// ---------------- helpers ----------------
__device__ __forceinline__ void mma_f16(float c[4], const unsigned a[4], const unsigned b[2]) {
    asm volatile(
        "mma.sync.aligned.m16n8k16.row.col.f32.f16.f16.f32 "
        "{%0,%1,%2,%3}, {%4,%5,%6,%7}, {%8,%9}, {%0,%1,%2,%3};\n"
        : "+f"(c[0]), "+f"(c[1]), "+f"(c[2]), "+f"(c[3])
        : "r"(a[0]), "r"(a[1]), "r"(a[2]), "r"(a[3]), "r"(b[0]), "r"(b[1]));
}

__device__ __forceinline__ void cp_async16(uint32_t saddr, const void* gptr, int szbytes) {
    asm volatile("cp.async.cg.shared.global [%0], [%1], 16, %2;\n"
                 :: "r"(saddr), "l"(gptr), "r"(szbytes));
}
#define CP_COMMIT() asm volatile("cp.async.commit_group;\n" ::)
#define CP_WAIT(n)  asm volatile("cp.async.wait_group %0;\n" :: "n"(n))

#define STS128U(addr, a, b, c, d) \
    asm volatile("st.shared.v4.b32 [%0], {%1, %2, %3, %4};" \
                 :: "r"(addr), "r"(a), "r"(b), "r"(c), "r"(d) : "memory")

__device__ __forceinline__ uint32_t pack_h2(float lo, float hi) {
    __half2 h = __floats2half2_rn(lo, hi);
    return *reinterpret_cast<uint32_t*>(&h);
}

// ---------------- kernel 0: zero output + counters ----------------
__global__ void init_kernel(float4* out4) {
    size_t i      = (size_t)blockIdx.x * blockDim.x + threadIdx.x;
    size_t stride = (size_t)gridDim.x * blockDim.x;
    const size_t n4 = OUT_ELEMS / 4;
    float4 z = make_float4(0.f, 0.f, 0.f, 0.f);
    for (size_t j = i; j < n4; j += stride) out4[j] = z;
    if (blockIdx.x == 0 && threadIdx.x < NE) g_cnt[threadIdx.x] = 0;
}

// ---------------- kernel 1: router ----------------
__global__ void router_kernel(const float* __restrict__ x,
                              const float* __restrict__ gate,
                              float* __restrict__ logits_out,
                              int write_logits) {
    int warp = threadIdx.x >> 5;
    int lane = threadIdx.x & 31;
    int tbase = blockIdx.x * 64 + warp * 8;

    for (int i = 0; i < 8; i++) {
        int t = tbase + i;
        const float4* xp = (const float4*)(x + (size_t)t * HID);
        float acc[NE];
#pragma unroll
        for (int e = 0; e < NE; e++) acc[e] = 0.f;
        for (int c = lane; c < HID / 4; c += 32) {
            float4 xv = __ldg(xp + c);
#pragma unroll
            for (int e = 0; e < NE; e++) {
                float4 gv = __ldg((const float4*)(gate + (size_t)e * HID) + c);
                acc[e] += xv.x * gv.x + xv.y * gv.y + xv.z * gv.z + xv.w * gv.w;
            }
        }
#pragma unroll
        for (int e = 0; e < NE; e++)
            for (int o = 16; o; o >>= 1) acc[e] += __shfl_xor_sync(0xffffffffu, acc[e], o);

        if (lane == 0) {
            float* lo = write_logits ? logits_out : g_logit_dump;
#pragma unroll
            for (int e = 0; e < NE; e++) lo[(size_t)t * NE + e] = acc[e];
            int e0 = 0;
            for (int e = 1; e < NE; e++) if (acc[e] > acc[e0]) e0 = e;
            int e1 = -1;
            for (int e = 0; e < NE; e++) {
                if (e == e0) continue;
                if (e1 < 0 || acc[e] > acc[e1]) e1 = e;
            }
            float w0 = 1.f / (1.f + expf(acc[e1] - acc[e0]));
            float w1 = 1.f - w0;
            g_sel[t * 2 + 0] = e0; g_selw[t * 2 + 0] = w0;
            g_sel[t * 2 + 1] = e1; g_selw[t * 2 + 1] = w1;
            atomicAdd(&g_cnt[e0], 1);
            atomicAdd(&g_cnt[e1], 1);
        }
    }
}

// ---------------- kernel 2: scan + tile list ----------------
__global__ void scan_kernel() {
    if (threadIdx.x == 0) {
        int o = 0, nt = 0;
        for (int e = 0; e < NE; e++) {
            g_off[e] = o;
            g_cur[e] = o;
            int c = g_cnt[e];
            int tl = (c + MT - 1) / MT;
            for (int m = 0; m < tl; m++) { g_tile_e[nt] = e; g_tile_m[nt] = m; nt++; }
            o += c;
        }
        g_ntiles = nt;
    }
}

// ---------------- kernel 3: scatter ----------------
__global__ void scatter_kernel() {
    int t = blockIdx.x * blockDim.x + threadIdx.x;
    if (t >= TOK) return;
#pragma unroll
    for (int k = 0; k < 2; k++) {
        int e = g_sel[t * 2 + k];
        int pos = atomicAdd(&g_cur[e], 1);
        g_ptok[pos] = t;
        g_pw[pos]   = g_selw[t * 2 + k];
        g_pe[pos]   = e;
    }
}

// ---------------- kernel 4: gather + scale divide -> fp16 ----------------
__global__ void gather_kernel(const float* __restrict__ x,
                              const float* __restrict__ scales) {
    int r = blockIdx.x;
    int tok = g_ptok[r];
    int e   = g_pe[r];
    const float4* xp = (const float4*)(x + (size_t)tok * HID);
    const float4* sp = (const float4*)(scales + (size_t)e * HID);
    uint32_t* dp = (uint32_t*)(g_xg + (size_t)r * HID);
    for (int c = threadIdx.x; c < HID / 4; c += blockDim.x) {
        float4 xv = xp[c], sv = sp[c];
        dp[c * 2 + 0] = pack_h2(xv.x / sv.x, xv.y / sv.y);
        dp[c * 2 + 1] = pack_h2(xv.z / sv.z, xv.w / sv.w);
    }
}

// ================== GEMM config (fp16 operands, fp32 accum) ==================
#define BKH     32                        // k per mainloop iter (halfs)
#define PADH    40                        // halfs per smem row (80B, conflict-free)
#define STAGES  4
#define A_STH   (MT * PADH)               // 10240 halfs per A stage
#define A_TOTH  (STAGES * A_STH)          // 40960 halfs
#define B_ROWS  128
#define B_STH   (B_ROWS * PADH)           // 5120 halfs per B buffer
#define SMEM_DYN ((A_TOTH + 2 * B_STH) * 2)   // 102400 B

// ---------------- kernel 5: GEMM-1: hmid = silu(xg@w1^T)*(xg@w3^T)*wr ----------------
// tile M=256, N=64 per matrix. 16 warps: 4 m x 4 n; warp 64m x 16n per matrix.
__global__ __launch_bounds__(512, 1) void gemm1_kernel(const float* __restrict__ w1,
                                                       const float* __restrict__ w3) {
    int ti = blockIdx.y;
    if (ti >= g_ntiles) return;
    int e    = g_tile_e[ti];
    int mt   = g_tile_m[ti];
    int cnt  = g_cnt[e];
    int off  = g_off[e];
    int row0 = off + mt * MT;
    int mrows = cnt - mt * MT; if (mrows > MT) mrows = MT;
    int n0 = blockIdx.x * 64;

    extern __shared__ __half sm[];
    uint32_t smb = (uint32_t)__cvta_generic_to_shared(sm);
    __half* Bsm = sm + A_TOTH;

    int tid  = threadIdx.x;
    int wid  = tid >> 5, lane = tid & 31;
    int wm   = (wid & 3) * 64;
    int wn   = (wid >> 2) * 16;
    int lr   = lane >> 2, lc = lane & 3;

    const float* w1p = w1 + ((size_t)e * FFN + n0) * HID;
    const float* w3p = w3 + ((size_t)e * FFN + n0) * HID;

    // B producer mapping: 128 rows x 4 col-chunks (8 halfs each); 1 chunk/thread
    int brow = tid >> 2, bc8 = tid & 3;
    const float* bsrc = ((brow < 64) ? (w1p + (size_t)brow * HID)
                                     : (w3p + (size_t)(brow - 64) * HID)) + bc8 * 8;
    uint32_t bdst = smb + (uint32_t)((A_TOTH + brow * PADH + bc8 * 8) * 2);

    float c1[4][2][4], c2[4][2][4];
#pragma unroll
    for (int i = 0; i < 4; i++)
#pragma unroll
        for (int j = 0; j < 2; j++)
#pragma unroll
            for (int q = 0; q < 4; q++) { c1[i][j][q] = 0.f; c2[i][j][q] = 0.f; }

    auto loadA = [&](int st, int k0) {
        uint32_t sb = smb + (uint32_t)(st * A_STH * 2);
#pragma unroll
        for (int j = 0; j < 2; j++) {
            int idx = j * 512 + tid;
            int row = idx >> 2, c8 = idx & 3;
            int p = (row < mrows) ? 16 : 0;
            cp_async16(sb + (uint32_t)((row * PADH + c8 * 8) * 2),
                       g_xg + (size_t)(row0 + row) * HID + k0 + c8 * 8, p);
        }
    };

    float4 rb0, rb1;
    auto ldgB = [&](int k0) {
        rb0 = *(const float4*)(bsrc + k0);
        rb1 = *(const float4*)(bsrc + k0 + 4);
    };
    auto stsB = [&](int buf) {
        STS128U(bdst + (uint32_t)(buf * B_STH * 2),
                pack_h2(rb0.x, rb0.y), pack_h2(rb0.z, rb0.w),
                pack_h2(rb1.x, rb1.y), pack_h2(rb1.z, rb1.w));
    };

    const int nk = HID / BKH;   // 64

    ldgB(0);
    loadA(0, 0);       CP_COMMIT();
    loadA(1, BKH);     CP_COMMIT();
    loadA(2, 2 * BKH); CP_COMMIT();
    stsB(0);
    ldgB(BKH);

    for (int i = 0; i < nk; i++) {
        CP_WAIT(2);
        __syncthreads();
        const __half* S  = sm + (i & 3) * A_STH;
        const __half* B1 = Bsm + (i & 1) * B_STH;
        const __half* B3 = B1 + 64 * PADH;
#pragma unroll
        for (int ko = 0; ko < BKH; ko += 16) {
            unsigned a[4][4], b1[2][2], b3[2][2];
#pragma unroll
            for (int s = 0; s < 4; s++) {
                int ar = wm + s * 16 + lr;
                a[s][0] = *(const uint32_t*)&S[ar * PADH + ko + 2 * lc];
                a[s][1] = *(const uint32_t*)&S[(ar + 8) * PADH + ko + 2 * lc];
                a[s][2] = *(const uint32_t*)&S[ar * PADH + ko + 8 + 2 * lc];
                a[s][3] = *(const uint32_t*)&S[(ar + 8) * PADH + ko + 8 + 2 * lc];
            }
#pragma unroll
            for (int sn = 0; sn < 2; sn++) {
                int br = wn + sn * 8 + lr;
                b1[sn][0] = *(const uint32_t*)&B1[br * PADH + ko + 2 * lc];
                b1[sn][1] = *(const uint32_t*)&B1[br * PADH + ko + 8 + 2 * lc];
                b3[sn][0] = *(const uint32_t*)&B3[br * PADH + ko + 2 * lc];
                b3[sn][1] = *(const uint32_t*)&B3[br * PADH + ko + 8 + 2 * lc];
            }
#pragma unroll
            for (int s = 0; s < 4; s++)
#pragma unroll
                for (int sn = 0; sn < 2; sn++) {
                    mma_f16(c1[s][sn], a[s], b1[sn]);
                    mma_f16(c2[s][sn], a[s], b3[sn]);
                }
        }
        if (i + 1 < nk) {
            stsB((i + 1) & 1);
            if (i + 2 < nk) ldgB((i + 2) * BKH);
        }
        if (i + 3 < nk) loadA((i + 3) & 3, (i + 3) * BKH);
        CP_COMMIT();
    }

    // epilogue: hmid = silu(c1) * c2 * wr -> fp16
#pragma unroll
    for (int s = 0; s < 4; s++) {
#pragma unroll
        for (int half = 0; half < 2; half++) {
            int r = wm + s * 16 + half * 8 + lr;
            if (r < mrows) {
                float wr = g_pw[row0 + r];
                __half* hp = g_hmid + (size_t)(row0 + r) * FFN + n0;
#pragma unroll
                for (int sn = 0; sn < 2; sn++) {
                    int col = wn + sn * 8 + lc * 2;
                    float v1a = c1[s][sn][half * 2 + 0], v3a = c2[s][sn][half * 2 + 0];
                    float v1b = c1[s][sn][half * 2 + 1], v3b = c2[s][sn][half * 2 + 1];
                    float oa = (v1a / (1.f + expf(-v1a))) * v3a * wr;
                    float ob = (v1b / (1.f + expf(-v1b))) * v3b * wr;
                    *(uint32_t*)(hp + col) = pack_h2(oa, ob);
                }
            }
        }
    }
}

// ---------------- kernel 6: GEMM-2: out += hmid @ w2^T (scatter-add) ----------------
// tile M=256, N=128. 16 warps: 4 m x 4 n; warp 64m x 32n.
__global__ __launch_bounds__(512, 1) void gemm2_kernel(const float* __restrict__ w2,
                                                       float* __restrict__ out) {
    int ti = blockIdx.y;
    if (ti >= g_ntiles) return;
    int e    = g_tile_e[ti];
    int mt   = g_tile_m[ti];
    int cnt  = g_cnt[e];
    int off  = g_off[e];
    int row0 = off + mt * MT;
    int mrows = cnt - mt * MT; if (mrows > MT) mrows = MT;
    int n0 = blockIdx.x * 128;

    extern __shared__ __half sm[];
    uint32_t smb = (uint32_t)__cvta_generic_to_shared(sm);
    __half* Bsm = sm + A_TOTH;

    int tid  = threadIdx.x;
    int wid  = tid >> 5, lane = tid & 31;
    int wm   = (wid & 3) * 64;
    int wn   = (wid >> 2) * 32;
    int lr   = lane >> 2, lc = lane & 3;

    const float* w2p = w2 + ((size_t)e * HID + n0) * FFN;

    int brow = tid >> 2, bc8 = tid & 3;
    const float* bsrc = w2p + (size_t)brow * FFN + bc8 * 8;
    uint32_t bdst = smb + (uint32_t)((A_TOTH + brow * PADH + bc8 * 8) * 2);

    float cc[4][4][4];
#pragma unroll
    for (int i = 0; i < 4; i++)
#pragma unroll
        for (int j = 0; j < 4; j++)
#pragma unroll
            for (int q = 0; q < 4; q++) cc[i][j][q] = 0.f;

    auto loadA = [&](int st, int k0) {
        uint32_t sb = smb + (uint32_t)(st * A_STH * 2);
#pragma unroll
        for (int j = 0; j < 2; j++) {
            int idx = j * 512 + tid;
            int row = idx >> 2, c8 = idx & 3;
            int p = (row < mrows) ? 16 : 0;
            cp_async16(sb + (uint32_t)((row * PADH + c8 * 8) * 2),
                       g_hmid + (size_t)(row0 + row) * FFN + k0 + c8 * 8, p);
        }
    };

    float4 rb0, rb1;
    auto ldgB = [&](int k0) {
        rb0 = *(const float4*)(bsrc + k0);
        rb1 = *(const float4*)(bsrc + k0 + 4);
    };
    auto stsB = [&](int buf) {
        STS128U(bdst + (uint32_t)(buf * B_STH * 2),
                pack_h2(rb0.x, rb0.y), pack_h2(rb0.z, rb0.w),
                pack_h2(rb1.x, rb1.y), pack_h2(rb1.z, rb1.w));
    };

    const int nk = FFN / BKH;   // 224

    ldgB(0);
    loadA(0, 0);       CP_COMMIT();
    loadA(1, BKH);     CP_COMMIT();
    loadA(2, 2 * BKH); CP_COMMIT();
    stsB(0);
    ldgB(BKH);

    for (int i = 0; i < nk; i++) {
        CP_WAIT(2);
        __syncthreads();
        const __half* S = sm + (i & 3) * A_STH;
        const __half* B = Bsm + (i & 1) * B_STH;
#pragma unroll
        for (int ko = 0; ko < BKH; ko += 16) {
            unsigned a[4][4], b[4][2];
#pragma unroll
            for (int s = 0; s < 4; s++) {
                int ar = wm + s * 16 + lr;
                a[s][0] = *(const uint32_t*)&S[ar * PADH + ko + 2 * lc];
                a[s][1] = *(const uint32_t*)&S[(ar + 8) * PADH + ko + 2 * lc];
                a[s][2] = *(const uint32_t*)&S[ar * PADH + ko + 8 + 2 * lc];
                a[s][3] = *(const uint32_t*)&S[(ar + 8) * PADH + ko + 8 + 2 * lc];
            }
#pragma unroll
            for (int sn = 0; sn < 4; sn++) {
                int br = wn + sn * 8 + lr;
                b[sn][0] = *(const uint32_t*)&B[br * PADH + ko + 2 * lc];
                b[sn][1] = *(const uint32_t*)&B[br * PADH + ko + 8 + 2 * lc];
            }
#pragma unroll
            for (int s = 0; s < 4; s++)
#pragma unroll
                for (int sn = 0; sn < 4; sn++)
                    mma_f16(cc[s][sn], a[s], b[sn]);
        }
        if (i + 1 < nk) {
            stsB((i + 1) & 1);
            if (i + 2 < nk) ldgB((i + 2) * BKH);
        }
        if (i + 3 < nk) loadA((i + 3) & 3, (i + 3) * BKH);
        CP_COMMIT();
    }

    // epilogue: atomic scatter-add into out[token][h]
#pragma unroll
    for (int s = 0; s < 4; s++) {
#pragma unroll
        for (int half = 0; half < 2; half++) {
            int r = wm + s * 16 + half * 8 + lr;
            if (r < mrows) {
                int tok = g_ptok[row0 + r];
                float* op = out + (size_t)tok * HID + n0;
#pragma unroll
                for (int sn = 0; sn < 4; sn++) {
                    int col = wn + sn * 8 + lc * 2;
                    atomicAdd(&op[col + 0], cc[s][sn][half * 2 + 0]);
                    atomicAdd(&op[col + 1], cc[s][sn][half * 2 + 1]);
                }
            }
        }
    }
}

// ---------------- host launch ----------------
extern "C" void kernel_launch(void* const* d_in, const int* in_sizes, int n_in,
                              void* d_out, int out_size) {
    const float* x      = (const float*)d_in[0];
    const float* gate   = (const float*)d_in[1];
    const float* w1     = (const float*)d_in[2];
    const float* w3     = (const float*)d_in[3];
    const float* w2     = (const float*)d_in[4];
    const float* scales = (const float*)d_in[5];

    float* out = (float*)d_out;
    int write_logits = ((size_t)out_size >= OUT_ELEMS + (size_t)TOK * NE) ? 1 : 0;
    float* logits = out + OUT_ELEMS;

    cudaFuncSetAttribute(gemm1_kernel, cudaFuncAttributeMaxDynamicSharedMemorySize, SMEM_DYN);
    cudaFuncSetAttribute(gemm2_kernel, cudaFuncAttributeMaxDynamicSharedMemorySize, SMEM_DYN);

    init_kernel<<<2048, 256>>>((float4*)out);
    router_kernel<<<TOK / 64, 256>>>(x, gate, logits, write_logits);
    scan_kernel<<<1, 32>>>();
    scatter_kernel<<<TOK / 256, 256>>>();
    gather_kernel<<<NPAIR, 128>>>(x, scales);

    dim3 g1(FFN / 64, MAXT);
    gemm1_kernel<<<g1, 512, SMEM_DYN>>>(w1, w3);

    dim3 g2(HID / 128, MAXT);
    gemm2_kernel<<<g2, 512, SMEM_DYN>>>(w2, out);
}

// round 8
// speedup vs baseline: 3.3015x; 1.0249x over previous
#include <cuda_runtime.h>
#include <cuda_fp16.h>
#include <cstdint>
#include <math.h>

// ---------------- problem constants ----------------
#define TOK      8192
#define HID      2048
#define FFN      7168
#define NE       8
#define NPAIR    (TOK * 2)
#define OUT_ELEMS ((size_t)TOK * HID)
#define MT       256            // GEMM m-tile rows
#define MAXT     72             // 16384/256 + NE

// ---------------- device scratch ----------------
__device__ int    g_cnt[NE];
__device__ int    g_off[NE];
__device__ int    g_cur[NE];
__device__ int    g_ntiles;
__device__ int    g_tile_e[MAXT];
__device__ int    g_tile_m[MAXT];
__device__ int    g_sel[NPAIR];
__device__ float  g_selw[NPAIR];
__device__ int    g_ptok[NPAIR];
__device__ float  g_pw[NPAIR];
__device__ int    g_pe[NPAIR];
__device__ float  g_logit_dump[TOK * NE];
__device__ __half g_xg[(size_t)NPAIR * HID];    // scaled activations, fp16
__device__ __half g_hmid[(size_t)NPAIR * FFN];  // silu(xw1)*(xw3)*wr, fp16

// ---------------- helpers ----------------
__device__ __forceinline__ void mma_f16(float c[4], const unsigned a[4], const unsigned b[2]) {
    asm volatile(
        "mma.sync.aligned.m16n8k16.row.col.f32.f16.f16.f32 "
        "{%0,%1,%2,%3}, {%4,%5,%6,%7}, {%8,%9}, {%0,%1,%2,%3};\n"
        : "+f"(c[0]), "+f"(c[1]), "+f"(c[2]), "+f"(c[3])
        : "r"(a[0]), "r"(a[1]), "r"(a[2]), "r"(a[3]), "r"(b[0]), "r"(b[1]));
}

#define LDSM_X4(r0, r1, r2, r3, addr) \
    asm volatile("ldmatrix.sync.aligned.m8n8.x4.shared.b16 {%0,%1,%2,%3}, [%4];" \
                 : "=r"(r0), "=r"(r1), "=r"(r2), "=r"(r3) : "r"(addr))

__device__ __forceinline__ void cp_async16(uint32_t saddr, const void* gptr, int szbytes) {
    asm volatile("cp.async.cg.shared.global [%0], [%1], 16, %2;\n"
                 :: "r"(saddr), "l"(gptr), "r"(szbytes));
}
#define CP_COMMIT() asm volatile("cp.async.commit_group;\n" ::)
#define CP_WAIT(n)  asm volatile("cp.async.wait_group %0;\n" :: "n"(n))

#define STS128U(addr, a, b, c, d) \
    asm volatile("st.shared.v4.b32 [%0], {%1, %2, %3, %4};" \
                 :: "r"(addr), "r"(a), "r"(b), "r"(c), "r"(d) : "memory")

__device__ __forceinline__ uint32_t pack_h2(float lo, float hi) {
    __half2 h = __floats2half2_rn(lo, hi);
    return *reinterpret_cast<uint32_t*>(&h);
}

// ---------------- kernel 0: zero output + counters ----------------
__global__ void init_kernel(float4* out4) {
    size_t i      = (size_t)blockIdx.x * blockDim.x + threadIdx.x;
    size_t stride = (size_t)gridDim.x * blockDim.x;
    const size_t n4 = OUT_ELEMS / 4;
    float4 z = make_float4(0.f, 0.f, 0.f, 0.f);
    for (size_t j = i; j < n4; j += stride) out4[j] = z;
    if (blockIdx.x == 0 && threadIdx.x < NE) g_cnt[threadIdx.x] = 0;
}

// ---------------- kernel 1: router ----------------
__global__ void router_kernel(const float* __restrict__ x,
                              const float* __restrict__ gate,
                              float* __restrict__ logits_out,
                              int write_logits) {
    int warp = threadIdx.x >> 5;
    int lane = threadIdx.x & 31;
    int tbase = blockIdx.x * 64 + warp * 8;

    for (int i = 0; i < 8; i++) {
        int t = tbase + i;
        const float4* xp = (const float4*)(x + (size_t)t * HID);
        float acc[NE];
#pragma unroll
        for (int e = 0; e < NE; e++) acc[e] = 0.f;
        for (int c = lane; c < HID / 4; c += 32) {
            float4 xv = __ldg(xp + c);
#pragma unroll
            for (int e = 0; e < NE; e++) {
                float4 gv = __ldg((const float4*)(gate + (size_t)e * HID) + c);
                acc[e] += xv.x * gv.x + xv.y * gv.y + xv.z * gv.z + xv.w * gv.w;
            }
        }
#pragma unroll
        for (int e = 0; e < NE; e++)
            for (int o = 16; o; o >>= 1) acc[e] += __shfl_xor_sync(0xffffffffu, acc[e], o);

        if (lane == 0) {
            float* lo = write_logits ? logits_out : g_logit_dump;
#pragma unroll
            for (int e = 0; e < NE; e++) lo[(size_t)t * NE + e] = acc[e];
            int e0 = 0;
            for (int e = 1; e < NE; e++) if (acc[e] > acc[e0]) e0 = e;
            int e1 = -1;
            for (int e = 0; e < NE; e++) {
                if (e == e0) continue;
                if (e1 < 0 || acc[e] > acc[e1]) e1 = e;
            }
            float w0 = 1.f / (1.f + expf(acc[e1] - acc[e0]));
            float w1 = 1.f - w0;
            g_sel[t * 2 + 0] = e0; g_selw[t * 2 + 0] = w0;
            g_sel[t * 2 + 1] = e1; g_selw[t * 2 + 1] = w1;
            atomicAdd(&g_cnt[e0], 1);
            atomicAdd(&g_cnt[e1], 1);
        }
    }
}

// ---------------- kernel 2: scan + tile list ----------------
__global__ void scan_kernel() {
    if (threadIdx.x == 0) {
        int o = 0, nt = 0;
        for (int e = 0; e < NE; e++) {
            g_off[e] = o;
            g_cur[e] = o;
            int c = g_cnt[e];
            int tl = (c + MT - 1) / MT;
            for (int m = 0; m < tl; m++) { g_tile_e[nt] = e; g_tile_m[nt] = m; nt++; }
            o += c;
        }
        g_ntiles = nt;
    }
}

// ---------------- kernel 3: scatter ----------------
__global__ void scatter_kernel() {
    int t = blockIdx.x * blockDim.x + threadIdx.x;
    if (t >= TOK) return;
#pragma unroll
    for (int k = 0; k < 2; k++) {
        int e = g_sel[t * 2 + k];
        int pos = atomicAdd(&g_cur[e], 1);
        g_ptok[pos] = t;
        g_pw[pos]   = g_selw[t * 2 + k];
        g_pe[pos]   = e;
    }
}

// ---------------- kernel 4: gather + scale divide -> fp16 ----------------
__global__ void gather_kernel(const float* __restrict__ x,
                              const float* __restrict__ scales) {
    int r = blockIdx.x;
    int tok = g_ptok[r];
    int e   = g_pe[r];
    const float4* xp = (const float4*)(x + (size_t)tok * HID);
    const float4* sp = (const float4*)(scales + (size_t)e * HID);
    uint32_t* dp = (uint32_t*)(g_xg + (size_t)r * HID);
    for (int c = threadIdx.x; c < HID / 4; c += blockDim.x) {
        float4 xv = xp[c], sv = sp[c];
        dp[c * 2 + 0] = pack_h2(xv.x / sv.x, xv.y / sv.y);
        dp[c * 2 + 1] = pack_h2(xv.z / sv.z, xv.w / sv.w);
    }
}

// ================== GEMM config (fp16 operands, fp32 accum) ==================
#define BKH     32                        // k per mainloop iter (halfs)
#define PADH    40                        // halfs per smem row (80B, conflict-free)
#define STAGES  4
#define A_STH   (MT * PADH)               // 10240 halfs per A stage
#define A_TOTH  (STAGES * A_STH)          // 40960 halfs
#define B_ROWS  128
#define B_STH   (B_ROWS * PADH)           // 5120 halfs per B buffer
#define SMEM_DYN ((A_TOTH + 2 * B_STH) * 2)   // 102400 B

// ---------------- kernel 5: GEMM-1: hmid = silu(xg@w1^T)*(xg@w3^T)*wr ----------------
// tile M=256, N=64 per matrix. 16 warps: 4 m x 4 n; warp 64m x 16n per matrix.
__global__ __launch_bounds__(512, 1) void gemm1_kernel(const float* __restrict__ w1,
                                                       const float* __restrict__ w3) {
    int ti = blockIdx.y;
    if (ti >= g_ntiles) return;
    int e    = g_tile_e[ti];
    int mt   = g_tile_m[ti];
    int cnt  = g_cnt[e];
    int off  = g_off[e];
    int row0 = off + mt * MT;
    int mrows = cnt - mt * MT; if (mrows > MT) mrows = MT;
    int n0 = blockIdx.x * 64;

    extern __shared__ __half sm[];
    uint32_t smb = (uint32_t)__cvta_generic_to_shared(sm);

    int tid  = threadIdx.x;
    int wid  = tid >> 5, lane = tid & 31;
    int wm   = (wid & 3) * 64;
    int wn   = (wid >> 2) * 16;
    int lr   = lane >> 2, lc = lane & 3;

    // ldmatrix lane offset within a 16x16 (halfs) fragment group
    uint32_t lm_off = (uint32_t)(((lane & 15) * PADH + (lane >> 4) * 8) * 2);

    const float* w1p = w1 + ((size_t)e * FFN + n0) * HID;
    const float* w3p = w3 + ((size_t)e * FFN + n0) * HID;

    // B producer mapping: 128 rows x 4 col-chunks (8 halfs each); 1 chunk/thread
    int brow = tid >> 2, bc8 = tid & 3;
    const float* bsrc = ((brow < 64) ? (w1p + (size_t)brow * HID)
                                     : (w3p + (size_t)(brow - 64) * HID)) + bc8 * 8;
    uint32_t bdst = smb + (uint32_t)((A_TOTH + brow * PADH + bc8 * 8) * 2);

    float c1[4][2][4], c2[4][2][4];
#pragma unroll
    for (int i = 0; i < 4; i++)
#pragma unroll
        for (int j = 0; j < 2; j++)
#pragma unroll
            for (int q = 0; q < 4; q++) { c1[i][j][q] = 0.f; c2[i][j][q] = 0.f; }

    auto loadA = [&](int st, int k0) {
        uint32_t sb = smb + (uint32_t)(st * A_STH * 2);
#pragma unroll
        for (int j = 0; j < 2; j++) {
            int idx = j * 512 + tid;
            int row = idx >> 2, c8 = idx & 3;
            int p = (row < mrows) ? 16 : 0;
            cp_async16(sb + (uint32_t)((row * PADH + c8 * 8) * 2),
                       g_xg + (size_t)(row0 + row) * HID + k0 + c8 * 8, p);
        }
    };

    float4 rb0, rb1;
    auto ldgB = [&](int k0) {
        rb0 = *(const float4*)(bsrc + k0);
        rb1 = *(const float4*)(bsrc + k0 + 4);
    };
    auto stsB = [&](int buf) {
        STS128U(bdst + (uint32_t)(buf * B_STH * 2),
                pack_h2(rb0.x, rb0.y), pack_h2(rb0.z, rb0.w),
                pack_h2(rb1.x, rb1.y), pack_h2(rb1.z, rb1.w));
    };

    const int nk = HID / BKH;   // 64

    ldgB(0);
    loadA(0, 0);       CP_COMMIT();
    loadA(1, BKH);     CP_COMMIT();
    loadA(2, 2 * BKH); CP_COMMIT();
    stsB(0);
    ldgB(BKH);

    for (int i = 0; i < nk; i++) {
        CP_WAIT(2);
        __syncthreads();
        uint32_t Sb = smb + (uint32_t)((i & 3) * A_STH * 2);
        uint32_t Bb = smb + (uint32_t)((A_TOTH + (i & 1) * B_STH) * 2);
#pragma unroll
        for (int ko = 0; ko < BKH; ko += 16) {
            unsigned a[4][4], b1[2][2], b3[2][2];
#pragma unroll
            for (int s = 0; s < 4; s++) {
                uint32_t ad = Sb + (uint32_t)(((wm + s * 16) * PADH + ko) * 2) + lm_off;
                LDSM_X4(a[s][0], a[s][1], a[s][2], a[s][3], ad);
            }
            {
                uint32_t bd1 = Bb + (uint32_t)((wn * PADH + ko) * 2) + lm_off;
                unsigned r0, r1, r2, r3;
                LDSM_X4(r0, r1, r2, r3, bd1);
                b1[0][0] = r0; b1[1][0] = r1; b1[0][1] = r2; b1[1][1] = r3;
                uint32_t bd3 = Bb + (uint32_t)(((64 + wn) * PADH + ko) * 2) + lm_off;
                LDSM_X4(r0, r1, r2, r3, bd3);
                b3[0][0] = r0; b3[1][0] = r1; b3[0][1] = r2; b3[1][1] = r3;
            }
#pragma unroll
            for (int s = 0; s < 4; s++)
#pragma unroll
                for (int sn = 0; sn < 2; sn++) {
                    mma_f16(c1[s][sn], a[s], b1[sn]);
                    mma_f16(c2[s][sn], a[s], b3[sn]);
                }
        }
        if (i + 1 < nk) {
            stsB((i + 1) & 1);
            if (i + 2 < nk) ldgB((i + 2) * BKH);
        }
        if (i + 3 < nk) loadA((i + 3) & 3, (i + 3) * BKH);
        CP_COMMIT();
    }

    // epilogue: hmid = silu(c1) * c2 * wr -> fp16
#pragma unroll
    for (int s = 0; s < 4; s++) {
#pragma unroll
        for (int half = 0; half < 2; half++) {
            int r = wm + s * 16 + half * 8 + lr;
            if (r < mrows) {
                float wr = g_pw[row0 + r];
                __half* hp = g_hmid + (size_t)(row0 + r) * FFN + n0;
#pragma unroll
                for (int sn = 0; sn < 2; sn++) {
                    int col = wn + sn * 8 + lc * 2;
                    float v1a = c1[s][sn][half * 2 + 0], v3a = c2[s][sn][half * 2 + 0];
                    float v1b = c1[s][sn][half * 2 + 1], v3b = c2[s][sn][half * 2 + 1];
                    float oa = (v1a / (1.f + expf(-v1a))) * v3a * wr;
                    float ob = (v1b / (1.f + expf(-v1b))) * v3b * wr;
                    *(uint32_t*)(hp + col) = pack_h2(oa, ob);
                }
            }
        }
    }
}

// ---------------- kernel 6: GEMM-2: out += hmid @ w2^T (scatter-add) ----------------
// tile M=256, N=128. 16 warps: 4 m x 4 n; warp 64m x 32n.
__global__ __launch_bounds__(512, 1) void gemm2_kernel(const float* __restrict__ w2,
                                                       float* __restrict__ out) {
    int ti = blockIdx.y;
    if (ti >= g_ntiles) return;
    int e    = g_tile_e[ti];
    int mt   = g_tile_m[ti];
    int cnt  = g_cnt[e];
    int off  = g_off[e];
    int row0 = off + mt * MT;
    int mrows = cnt - mt * MT; if (mrows > MT) mrows = MT;
    int n0 = blockIdx.x * 128;

    extern __shared__ __half sm[];
    uint32_t smb = (uint32_t)__cvta_generic_to_shared(sm);

    int tid  = threadIdx.x;
    int wid  = tid >> 5, lane = tid & 31;
    int wm   = (wid & 3) * 64;
    int wn   = (wid >> 2) * 32;
    int lr   = lane >> 2, lc = lane & 3;

    uint32_t lm_off = (uint32_t)(((lane & 15) * PADH + (lane >> 4) * 8) * 2);

    const float* w2p = w2 + ((size_t)e * HID + n0) * FFN;

    int brow = tid >> 2, bc8 = tid & 3;
    const float* bsrc = w2p + (size_t)brow * FFN + bc8 * 8;
    uint32_t bdst = smb + (uint32_t)((A_TOTH + brow * PADH + bc8 * 8) * 2);

    float cc[4][4][4];
#pragma unroll
    for (int i = 0; i < 4; i++)
#pragma unroll
        for (int j = 0; j < 4; j++)
#pragma unroll
            for (int q = 0; q < 4; q++) cc[i][j][q] = 0.f;

    auto loadA = [&](int st, int k0) {
        uint32_t sb = smb + (uint32_t)(st * A_STH * 2);
#pragma unroll
        for (int j = 0; j < 2; j++) {
            int idx = j * 512 + tid;
            int row = idx >> 2, c8 = idx & 3;
            int p = (row < mrows) ? 16 : 0;
            cp_async16(sb + (uint32_t)((row * PADH + c8 * 8) * 2),
                       g_hmid + (size_t)(row0 + row) * FFN + k0 + c8 * 8, p);
        }
    };

    float4 rb0, rb1;
    auto ldgB = [&](int k0) {
        rb0 = *(const float4*)(bsrc + k0);
        rb1 = *(const float4*)(bsrc + k0 + 4);
    };
    auto stsB = [&](int buf) {
        STS128U(bdst + (uint32_t)(buf * B_STH * 2),
                pack_h2(rb0.x, rb0.y), pack_h2(rb0.z, rb0.w),
                pack_h2(rb1.x, rb1.y), pack_h2(rb1.z, rb1.w));
    };

    const int nk = FFN / BKH;   // 224

    ldgB(0);
    loadA(0, 0);       CP_COMMIT();
    loadA(1, BKH);     CP_COMMIT();
    loadA(2, 2 * BKH); CP_COMMIT();
    stsB(0);
    ldgB(BKH);

    for (int i = 0; i < nk; i++) {
        CP_WAIT(2);
        __syncthreads();
        uint32_t Sb = smb + (uint32_t)((i & 3) * A_STH * 2);
        uint32_t Bb = smb + (uint32_t)((A_TOTH + (i & 1) * B_STH) * 2);
#pragma unroll
        for (int ko = 0; ko < BKH; ko += 16) {
            unsigned a[4][4], b[4][2];
#pragma unroll
            for (int s = 0; s < 4; s++) {
                uint32_t ad = Sb + (uint32_t)(((wm + s * 16) * PADH + ko) * 2) + lm_off;
                LDSM_X4(a[s][0], a[s][1], a[s][2], a[s][3], ad);
            }
            {
                unsigned r0, r1, r2, r3;
                uint32_t bd0 = Bb + (uint32_t)((wn * PADH + ko) * 2) + lm_off;
                LDSM_X4(r0, r1, r2, r3, bd0);
                b[0][0] = r0; b[1][0] = r1; b[0][1] = r2; b[1][1] = r3;
                uint32_t bd1 = Bb + (uint32_t)(((wn + 16) * PADH + ko) * 2) + lm_off;
                LDSM_X4(r0, r1, r2, r3, bd1);
                b[2][0] = r0; b[3][0] = r1; b[2][1] = r2; b[3][1] = r3;
            }
#pragma unroll
            for (int s = 0; s < 4; s++)
#pragma unroll
                for (int sn = 0; sn < 4; sn++)
                    mma_f16(cc[s][sn], a[s], b[sn]);
        }
        if (i + 1 < nk) {
            stsB((i + 1) & 1);
            if (i + 2 < nk) ldgB((i + 2) * BKH);
        }
        if (i + 3 < nk) loadA((i + 3) & 3, (i + 3) * BKH);
        CP_COMMIT();
    }

    // epilogue: atomic scatter-add into out[token][h]
#pragma unroll
    for (int s = 0; s < 4; s++) {
#pragma unroll
        for (int half = 0; half < 2; half++) {
            int r = wm + s * 16 + half * 8 + lr;
            if (r < mrows) {
                int tok = g_ptok[row0 + r];
                float* op = out + (size_t)tok * HID + n0;
#pragma unroll
                for (int sn = 0; sn < 4; sn++) {
                    int col = wn + sn * 8 + lc * 2;
                    atomicAdd(&op[col + 0], cc[s][sn][half * 2 + 0]);
                    atomicAdd(&op[col + 1], cc[s][sn][half * 2 + 1]);
                }
            }
        }
    }
}

// ---------------- host launch ----------------
extern "C" void kernel_launch(void* const* d_in, const int* in_sizes, int n_in,
                              void* d_out, int out_size) {
    const float* x      = (const float*)d_in[0];
    const float* gate   = (const float*)d_in[1];
    const float* w1     = (const float*)d_in[2];
    const float* w3     = (const float*)d_in[3];
    const float* w2     = (const float*)d_in[4];
    const float* scales = (const float*)d_in[5];

    float* out = (float*)d_out;
    int write_logits = ((size_t)out_size >= OUT_ELEMS + (size_t)TOK * NE) ? 1 : 0;
    float* logits = out + OUT_ELEMS;

    cudaFuncSetAttribute(gemm1_kernel, cudaFuncAttributeMaxDynamicSharedMemorySize, SMEM_DYN);
    cudaFuncSetAttribute(gemm2_kernel, cudaFuncAttributeMaxDynamicSharedMemorySize, SMEM_DYN);

    init_kernel<<<2048, 256>>>((float4*)out);
    router_kernel<<<TOK / 64, 256>>>(x, gate, logits, write_logits);
    scan_kernel<<<1, 32>>>();
    scatter_kernel<<<TOK / 256, 256>>>();
    gather_kernel<<<NPAIR, 128>>>(x, scales);

    dim3 g1(FFN / 64, MAXT);
    gemm1_kernel<<<g1, 512, SMEM_DYN>>>(w1, w3);

    dim3 g2(HID / 128, MAXT);
    gemm2_kernel<<<g2, 512, SMEM_DYN>>>(w2, out);
}

// round 9
// speedup vs baseline: 3.3289x; 1.0083x over previous
#include <cuda_runtime.h>
#include <cuda_fp16.h>
#include <cstdint>
#include <math.h>

// ---------------- problem constants ----------------
#define TOK      8192
#define HID      2048
#define FFN      7168
#define NE       8
#define NPAIR    (TOK * 2)
#define OUT_ELEMS ((size_t)TOK * HID)
#define MT       256            // GEMM m-tile rows
#define MAXT     72             // 16384/256 + NE
#define NCHUNK1  (FFN / 64)     // 112 gemm1 n-chunks per m-tile
#define NCHUNK2  (HID / 128)    // 16 gemm2 n-chunks per m-tile

// ---------------- device scratch ----------------
__device__ int      g_cnt[NE];
__device__ int      g_off[NE];
__device__ int      g_cur[NE];
__device__ int      g_ntiles;
__device__ int      g_tile_e[MAXT];
__device__ int      g_tile_m[MAXT];
__device__ int      g_sel[NPAIR];
__device__ float    g_selw[NPAIR];
__device__ int      g_ptok[NPAIR];
__device__ float    g_pw[NPAIR];
__device__ int      g_pe[NPAIR];
__device__ float    g_logit_dump[TOK * NE];
__device__ __half   g_xg[(size_t)NPAIR * HID];    // scaled activations, fp16
__device__ __half   g_hmid[(size_t)NPAIR * FFN];  // silu(xw1)*(xw3)*wr, fp16
__device__ unsigned g_qhead;                      // work-queue head
__device__ unsigned g_done1[MAXT];                // per-m-tile gemm1 completion count
__device__ int      g_n1, g_ntotal;               // queue sizes

// ---------------- helpers ----------------
__device__ __forceinline__ void mma_f16(float c[4], const unsigned a[4], const unsigned b[2]) {
    asm volatile(
        "mma.sync.aligned.m16n8k16.row.col.f32.f16.f16.f32 "
        "{%0,%1,%2,%3}, {%4,%5,%6,%7}, {%8,%9}, {%0,%1,%2,%3};\n"
        : "+f"(c[0]), "+f"(c[1]), "+f"(c[2]), "+f"(c[3])
        : "r"(a[0]), "r"(a[1]), "r"(a[2]), "r"(a[3]), "r"(b[0]), "r"(b[1]));
}

#define LDSM_X4(r0, r1, r2, r3, addr) \
    asm volatile("ldmatrix.sync.aligned.m8n8.x4.shared.b16 {%0,%1,%2,%3}, [%4];" \
                 : "=r"(r0), "=r"(r1), "=r"(r2), "=r"(r3) : "r"(addr))

__device__ __forceinline__ void cp_async16(uint32_t saddr, const void* gptr, int szbytes) {
    asm volatile("cp.async.cg.shared.global [%0], [%1], 16, %2;\n"
                 :: "r"(saddr), "l"(gptr), "r"(szbytes));
}
#define CP_COMMIT() asm volatile("cp.async.commit_group;\n" ::)
#define CP_WAIT(n)  asm volatile("cp.async.wait_group %0;\n" :: "n"(n))

#define STS128U(addr, a, b, c, d) \
    asm volatile("st.shared.v4.b32 [%0], {%1, %2, %3, %4};" \
                 :: "r"(addr), "r"(a), "r"(b), "r"(c), "r"(d) : "memory")

__device__ __forceinline__ uint32_t pack_h2(float lo, float hi) {
    __half2 h = __floats2half2_rn(lo, hi);
    return *reinterpret_cast<uint32_t*>(&h);
}

// ---------------- kernel 0: zero output + counters ----------------
__global__ void init_kernel(float4* out4) {
    size_t i      = (size_t)blockIdx.x * blockDim.x + threadIdx.x;
    size_t stride = (size_t)gridDim.x * blockDim.x;
    const size_t n4 = OUT_ELEMS / 4;
    float4 z = make_float4(0.f, 0.f, 0.f, 0.f);
    for (size_t j = i; j < n4; j += stride) out4[j] = z;
    if (blockIdx.x == 0 && threadIdx.x < NE) g_cnt[threadIdx.x] = 0;
}

// ---------------- kernel 1: router ----------------
__global__ void router_kernel(const float* __restrict__ x,
                              const float* __restrict__ gate,
                              float* __restrict__ logits_out,
                              int write_logits) {
    int warp = threadIdx.x >> 5;
    int lane = threadIdx.x & 31;
    int tbase = blockIdx.x * 64 + warp * 8;

    for (int i = 0; i < 8; i++) {
        int t = tbase + i;
        const float4* xp = (const float4*)(x + (size_t)t * HID);
        float acc[NE];
#pragma unroll
        for (int e = 0; e < NE; e++) acc[e] = 0.f;
        for (int c = lane; c < HID / 4; c += 32) {
            float4 xv = __ldg(xp + c);
#pragma unroll
            for (int e = 0; e < NE; e++) {
                float4 gv = __ldg((const float4*)(gate + (size_t)e * HID) + c);
                acc[e] += xv.x * gv.x + xv.y * gv.y + xv.z * gv.z + xv.w * gv.w;
            }
        }
#pragma unroll
        for (int e = 0; e < NE; e++)
            for (int o = 16; o; o >>= 1) acc[e] += __shfl_xor_sync(0xffffffffu, acc[e], o);

        if (lane == 0) {
            float* lo = write_logits ? logits_out : g_logit_dump;
#pragma unroll
            for (int e = 0; e < NE; e++) lo[(size_t)t * NE + e] = acc[e];
            int e0 = 0;
            for (int e = 1; e < NE; e++) if (acc[e] > acc[e0]) e0 = e;
            int e1 = -1;
            for (int e = 0; e < NE; e++) {
                if (e == e0) continue;
                if (e1 < 0 || acc[e] > acc[e1]) e1 = e;
            }
            float w0 = 1.f / (1.f + expf(acc[e1] - acc[e0]));
            float w1 = 1.f - w0;
            g_sel[t * 2 + 0] = e0; g_selw[t * 2 + 0] = w0;
            g_sel[t * 2 + 1] = e1; g_selw[t * 2 + 1] = w1;
            atomicAdd(&g_cnt[e0], 1);
            atomicAdd(&g_cnt[e1], 1);
        }
    }
}

// ---------------- kernel 2: scan + tile list + queue reset ----------------
__global__ void scan_kernel() {
    if (threadIdx.x == 0) {
        int o = 0, nt = 0;
        for (int e = 0; e < NE; e++) {
            g_off[e] = o;
            g_cur[e] = o;
            int c = g_cnt[e];
            int tl = (c + MT - 1) / MT;
            for (int m = 0; m < tl; m++) { g_tile_e[nt] = e; g_tile_m[nt] = m; nt++; }
            o += c;
        }
        g_ntiles = nt;
        g_n1     = nt * NCHUNK1;
        g_ntotal = nt * NCHUNK1 + nt * NCHUNK2;
        g_qhead  = 0;
    }
    for (int i = threadIdx.x; i < MAXT; i += blockDim.x) g_done1[i] = 0;
}

// ---------------- kernel 3: scatter ----------------
__global__ void scatter_kernel() {
    int t = blockIdx.x * blockDim.x + threadIdx.x;
    if (t >= TOK) return;
#pragma unroll
    for (int k = 0; k < 2; k++) {
        int e = g_sel[t * 2 + k];
        int pos = atomicAdd(&g_cur[e], 1);
        g_ptok[pos] = t;
        g_pw[pos]   = g_selw[t * 2 + k];
        g_pe[pos]   = e;
    }
}

// ---------------- kernel 4: gather + scale divide -> fp16 ----------------
__global__ void gather_kernel(const float* __restrict__ x,
                              const float* __restrict__ scales) {
    int r = blockIdx.x;
    int tok = g_ptok[r];
    int e   = g_pe[r];
    const float4* xp = (const float4*)(x + (size_t)tok * HID);
    const float4* sp = (const float4*)(scales + (size_t)e * HID);
    uint32_t* dp = (uint32_t*)(g_xg + (size_t)r * HID);
    for (int c = threadIdx.x; c < HID / 4; c += blockDim.x) {
        float4 xv = xp[c], sv = sp[c];
        dp[c * 2 + 0] = pack_h2(xv.x / sv.x, xv.y / sv.y);
        dp[c * 2 + 1] = pack_h2(xv.z / sv.z, xv.w / sv.w);
    }
}

// ================== GEMM config (fp16 operands, fp32 accum) ==================
#define BKH     32                        // k per mainloop iter (halfs)
#define PADH    40                        // halfs per smem row (80B, conflict-free)
#define STAGES  4
#define A_STH   (MT * PADH)               // 10240 halfs per A stage
#define A_TOTH  (STAGES * A_STH)          // 40960 halfs
#define B_ROWS  128
#define B_STH   (B_ROWS * PADH)           // 5120 halfs per B buffer
#define SMEM_DYN ((A_TOTH + 2 * B_STH) * 2)   // 102400 B

// ---------------- gemm1 tile: hmid[ti, n-chunk] = silu(xg@w1^T)*(xg@w3^T)*wr ----------------
__device__ void gemm1_tile(int ti, int nx,
                           const float* __restrict__ w1,
                           const float* __restrict__ w3) {
    int e    = g_tile_e[ti];
    int mt   = g_tile_m[ti];
    int cnt  = g_cnt[e];
    int off  = g_off[e];
    int row0 = off + mt * MT;
    int mrows = cnt - mt * MT; if (mrows > MT) mrows = MT;
    int n0 = nx * 64;

    extern __shared__ __half sm[];
    uint32_t smb = (uint32_t)__cvta_generic_to_shared(sm);

    int tid  = threadIdx.x;
    int wid  = tid >> 5, lane = tid & 31;
    int wm   = (wid & 3) * 64;
    int wn   = (wid >> 2) * 16;
    int lr   = lane >> 2, lc = lane & 3;

    uint32_t lm_off = (uint32_t)(((lane & 15) * PADH + (lane >> 4) * 8) * 2);

    const float* w1p = w1 + ((size_t)e * FFN + n0) * HID;
    const float* w3p = w3 + ((size_t)e * FFN + n0) * HID;

    int brow = tid >> 2, bc8 = tid & 3;
    const float* bsrc = ((brow < 64) ? (w1p + (size_t)brow * HID)
                                     : (w3p + (size_t)(brow - 64) * HID)) + bc8 * 8;
    uint32_t bdst = smb + (uint32_t)((A_TOTH + brow * PADH + bc8 * 8) * 2);

    float c1[4][2][4], c2[4][2][4];
#pragma unroll
    for (int i = 0; i < 4; i++)
#pragma unroll
        for (int j = 0; j < 2; j++)
#pragma unroll
            for (int q = 0; q < 4; q++) { c1[i][j][q] = 0.f; c2[i][j][q] = 0.f; }

    auto loadA = [&](int st, int k0) {
        uint32_t sb = smb + (uint32_t)(st * A_STH * 2);
#pragma unroll
        for (int j = 0; j < 2; j++) {
            int idx = j * 512 + tid;
            int row = idx >> 2, c8 = idx & 3;
            int p = (row < mrows) ? 16 : 0;
            cp_async16(sb + (uint32_t)((row * PADH + c8 * 8) * 2),
                       g_xg + (size_t)(row0 + row) * HID + k0 + c8 * 8, p);
        }
    };

    float4 rb0, rb1;
    auto ldgB = [&](int k0) {
        rb0 = *(const float4*)(bsrc + k0);
        rb1 = *(const float4*)(bsrc + k0 + 4);
    };
    auto stsB = [&](int buf) {
        STS128U(bdst + (uint32_t)(buf * B_STH * 2),
                pack_h2(rb0.x, rb0.y), pack_h2(rb0.z, rb0.w),
                pack_h2(rb1.x, rb1.y), pack_h2(rb1.z, rb1.w));
    };

    const int nk = HID / BKH;   // 64

    ldgB(0);
    loadA(0, 0);       CP_COMMIT();
    loadA(1, BKH);     CP_COMMIT();
    loadA(2, 2 * BKH); CP_COMMIT();
    stsB(0);
    ldgB(BKH);

    for (int i = 0; i < nk; i++) {
        CP_WAIT(2);
        __syncthreads();
        uint32_t Sb = smb + (uint32_t)((i & 3) * A_STH * 2);
        uint32_t Bb = smb + (uint32_t)((A_TOTH + (i & 1) * B_STH) * 2);
#pragma unroll
        for (int ko = 0; ko < BKH; ko += 16) {
            unsigned a[4][4], b1[2][2], b3[2][2];
#pragma unroll
            for (int s = 0; s < 4; s++) {
                uint32_t ad = Sb + (uint32_t)(((wm + s * 16) * PADH + ko) * 2) + lm_off;
                LDSM_X4(a[s][0], a[s][1], a[s][2], a[s][3], ad);
            }
            {
                uint32_t bd1 = Bb + (uint32_t)((wn * PADH + ko) * 2) + lm_off;
                unsigned r0, r1, r2, r3;
                LDSM_X4(r0, r1, r2, r3, bd1);
                b1[0][0] = r0; b1[1][0] = r1; b1[0][1] = r2; b1[1][1] = r3;
                uint32_t bd3 = Bb + (uint32_t)(((64 + wn) * PADH + ko) * 2) + lm_off;
                LDSM_X4(r0, r1, r2, r3, bd3);
                b3[0][0] = r0; b3[1][0] = r1; b3[0][1] = r2; b3[1][1] = r3;
            }
#pragma unroll
            for (int s = 0; s < 4; s++)
#pragma unroll
                for (int sn = 0; sn < 2; sn++) {
                    mma_f16(c1[s][sn], a[s], b1[sn]);
                    mma_f16(c2[s][sn], a[s], b3[sn]);
                }
        }
        if (i + 1 < nk) {
            stsB((i + 1) & 1);
            if (i + 2 < nk) ldgB((i + 2) * BKH);
        }
        if (i + 3 < nk) loadA((i + 3) & 3, (i + 3) * BKH);
        CP_COMMIT();
    }
    CP_WAIT(0);

    // epilogue: hmid = silu(c1) * c2 * wr -> fp16
#pragma unroll
    for (int s = 0; s < 4; s++) {
#pragma unroll
        for (int half = 0; half < 2; half++) {
            int r = wm + s * 16 + half * 8 + lr;
            if (r < mrows) {
                float wr = g_pw[row0 + r];
                __half* hp = g_hmid + (size_t)(row0 + r) * FFN + n0;
#pragma unroll
                for (int sn = 0; sn < 2; sn++) {
                    int col = wn + sn * 8 + lc * 2;
                    float v1a = c1[s][sn][half * 2 + 0], v3a = c2[s][sn][half * 2 + 0];
                    float v1b = c1[s][sn][half * 2 + 1], v3b = c2[s][sn][half * 2 + 1];
                    float oa = (v1a / (1.f + expf(-v1a))) * v3a * wr;
                    float ob = (v1b / (1.f + expf(-v1b))) * v3b * wr;
                    *(uint32_t*)(hp + col) = pack_h2(oa, ob);
                }
            }
        }
    }

    // publish: hmid stores visible, then bump completion counter
    __threadfence();
    __syncthreads();
    if (tid == 0) atomicAdd(&g_done1[ti], 1u);
}

// ---------------- gemm2 tile: out[tok, n-chunk] += hmid @ w2^T ----------------
__device__ void gemm2_tile(int ti, int nx,
                           const float* __restrict__ w2,
                           float* __restrict__ out) {
    int e    = g_tile_e[ti];
    int mt   = g_tile_m[ti];
    int cnt  = g_cnt[e];
    int off  = g_off[e];
    int row0 = off + mt * MT;
    int mrows = cnt - mt * MT; if (mrows > MT) mrows = MT;
    int n0 = nx * 128;

    // wait for all gemm1 chunks of this m-tile
    if (threadIdx.x == 0) {
        while (atomicAdd(&g_done1[ti], 0u) < (unsigned)NCHUNK1) __nanosleep(200);
    }
    __syncthreads();
    __threadfence();

    extern __shared__ __half sm[];
    uint32_t smb = (uint32_t)__cvta_generic_to_shared(sm);

    int tid  = threadIdx.x;
    int wid  = tid >> 5, lane = tid & 31;
    int wm   = (wid & 3) * 64;
    int wn   = (wid >> 2) * 32;
    int lr   = lane >> 2, lc = lane & 3;

    uint32_t lm_off = (uint32_t)(((lane & 15) * PADH + (lane >> 4) * 8) * 2);

    const float* w2p = w2 + ((size_t)e * HID + n0) * FFN;

    int brow = tid >> 2, bc8 = tid & 3;
    const float* bsrc = w2p + (size_t)brow * FFN + bc8 * 8;
    uint32_t bdst = smb + (uint32_t)((A_TOTH + brow * PADH + bc8 * 8) * 2);

    float cc[4][4][4];
#pragma unroll
    for (int i = 0; i < 4; i++)
#pragma unroll
        for (int j = 0; j < 4; j++)
#pragma unroll
            for (int q = 0; q < 4; q++) cc[i][j][q] = 0.f;

    auto loadA = [&](int st, int k0) {
        uint32_t sb = smb + (uint32_t)(st * A_STH * 2);
#pragma unroll
        for (int j = 0; j < 2; j++) {
            int idx = j * 512 + tid;
            int row = idx >> 2, c8 = idx & 3;
            int p = (row < mrows) ? 16 : 0;
            cp_async16(sb + (uint32_t)((row * PADH + c8 * 8) * 2),
                       g_hmid + (size_t)(row0 + row) * FFN + k0 + c8 * 8, p);
        }
    };

    float4 rb0, rb1;
    auto ldgB = [&](int k0) {
        rb0 = *(const float4*)(bsrc + k0);
        rb1 = *(const float4*)(bsrc + k0 + 4);
    };
    auto stsB = [&](int buf) {
        STS128U(bdst + (uint32_t)(buf * B_STH * 2),
                pack_h2(rb0.x, rb0.y), pack_h2(rb0.z, rb0.w),
                pack_h2(rb1.x, rb1.y), pack_h2(rb1.z, rb1.w));
    };

    const int nk = FFN / BKH;   // 224

    ldgB(0);
    loadA(0, 0);       CP_COMMIT();
    loadA(1, BKH);     CP_COMMIT();
    loadA(2, 2 * BKH); CP_COMMIT();
    stsB(0);
    ldgB(BKH);

    for (int i = 0; i < nk; i++) {
        CP_WAIT(2);
        __syncthreads();
        uint32_t Sb = smb + (uint32_t)((i & 3) * A_STH * 2);
        uint32_t Bb = smb + (uint32_t)((A_TOTH + (i & 1) * B_STH) * 2);
#pragma unroll
        for (int ko = 0; ko < BKH; ko += 16) {
            unsigned a[4][4], b[4][2];
#pragma unroll
            for (int s = 0; s < 4; s++) {
                uint32_t ad = Sb + (uint32_t)(((wm + s * 16) * PADH + ko) * 2) + lm_off;
                LDSM_X4(a[s][0], a[s][1], a[s][2], a[s][3], ad);
            }
            {
                unsigned r0, r1, r2, r3;
                uint32_t bd0 = Bb + (uint32_t)((wn * PADH + ko) * 2) + lm_off;
                LDSM_X4(r0, r1, r2, r3, bd0);
                b[0][0] = r0; b[1][0] = r1; b[0][1] = r2; b[1][1] = r3;
                uint32_t bd1 = Bb + (uint32_t)(((wn + 16) * PADH + ko) * 2) + lm_off;
                LDSM_X4(r0, r1, r2, r3, bd1);
                b[2][0] = r0; b[3][0] = r1; b[2][1] = r2; b[3][1] = r3;
            }
#pragma unroll
            for (int s = 0; s < 4; s++)
#pragma unroll
                for (int sn = 0; sn < 4; sn++)
                    mma_f16(cc[s][sn], a[s], b[sn]);
        }
        if (i + 1 < nk) {
            stsB((i + 1) & 1);
            if (i + 2 < nk) ldgB((i + 2) * BKH);
        }
        if (i + 3 < nk) loadA((i + 3) & 3, (i + 3) * BKH);
        CP_COMMIT();
    }
    CP_WAIT(0);

    // epilogue: atomic scatter-add into out[token][h]
#pragma unroll
    for (int s = 0; s < 4; s++) {
#pragma unroll
        for (int half = 0; half < 2; half++) {
            int r = wm + s * 16 + half * 8 + lr;
            if (r < mrows) {
                int tok = g_ptok[row0 + r];
                float* op = out + (size_t)tok * HID + n0;
#pragma unroll
                for (int sn = 0; sn < 4; sn++) {
                    int col = wn + sn * 8 + lc * 2;
                    atomicAdd(&op[col + 0], cc[s][sn][half * 2 + 0]);
                    atomicAdd(&op[col + 1], cc[s][sn][half * 2 + 1]);
                }
            }
        }
    }
}

// ---------------- fused persistent GEMM kernel ----------------
__global__ __launch_bounds__(512, 1) void mm_kernel(const float* __restrict__ w1,
                                                    const float* __restrict__ w3,
                                                    const float* __restrict__ w2,
                                                    float* __restrict__ out) {
    __shared__ int s_item;
    const int n1   = g_n1;
    const int ntot = g_ntotal;

    while (true) {
        __syncthreads();   // all warps done with previous item's smem
        if (threadIdx.x == 0) s_item = (int)atomicAdd(&g_qhead, 1u);
        __syncthreads();
        int id = s_item;
        if (id >= ntot) break;
        if (id < n1) {
            gemm1_tile(id / NCHUNK1, id % NCHUNK1, w1, w3);
        } else {
            int id2 = id - n1;
            gemm2_tile(id2 / NCHUNK2, id2 % NCHUNK2, w2, out);
        }
    }
}

// ---------------- host launch ----------------
extern "C" void kernel_launch(void* const* d_in, const int* in_sizes, int n_in,
                              void* d_out, int out_size) {
    const float* x      = (const float*)d_in[0];
    const float* gate   = (const float*)d_in[1];
    const float* w1     = (const float*)d_in[2];
    const float* w3     = (const float*)d_in[3];
    const float* w2     = (const float*)d_in[4];
    const float* scales = (const float*)d_in[5];

    float* out = (float*)d_out;
    int write_logits = ((size_t)out_size >= OUT_ELEMS + (size_t)TOK * NE) ? 1 : 0;
    float* logits = out + OUT_ELEMS;

    cudaFuncSetAttribute(mm_kernel, cudaFuncAttributeMaxDynamicSharedMemorySize, SMEM_DYN);

    init_kernel<<<2048, 256>>>((float4*)out);
    router_kernel<<<TOK / 64, 256>>>(x, gate, logits, write_logits);
    scan_kernel<<<1, 128>>>();
    scatter_kernel<<<TOK / 256, 256>>>();
    gather_kernel<<<NPAIR, 128>>>(x, scales);

    mm_kernel<<<152, 512, SMEM_DYN>>>(w1, w3, w2, out);
}